// round 14
// baseline (speedup 1.0000x reference)
#include <cuda_runtime.h>
#include <math.h>

#define EPS 1e-5f

// ---------------- scratch pool (floats) ----------------
#define OF_VOLA   0ull
#define OF_VOLB   25165824ull
#define OF_QKV    50331648ull
#define OF_XATT   88080384ull
#define OF_AOUT   100663296ull
#define OF_VOLP   113246208ull
#define OF_YV     125829120ull
#define OF_S12    138412032ull
#define OF_PCS    139984896ull
#define OF_PCQ    140771328ull
#define OF_PPOOL  141557760ull
#define OF_P12S   142344192ull
#define OF_P12Q   142368768ull
#define OF_PYS    142393344ull
#define OF_PYQ    142589952ull
#define OF_M1     142786560ull
#define OF_R1     142787328ull
#define OF_POOLED 142788096ull
#define OF_M2     142788864ull
#define OF_R2     142788912ull
#define OF_M3     142788960ull
#define OF_R3     142789344ull
#define OF_GATE   142789728ull
#define OF_BIAS   142790144ull   // 24576
#define OF_WEMB   142814720ull   // 192*288 = 55296
#define OF_WQKV   142870016ull   // 96*288  = 27648
#define OF_WPROJ  142897664ull   // 192*192 = 36864
#define OF_WPJ    142934528ull   // 192*96  = 18432
#define OF_ZROW   142952960ull   // 6144 zeros (32*192)

__device__ float g_pool[143000000];

__device__ __forceinline__ float geluf(float x) {
    return 0.5f * x * (1.0f + erff(x * 0.70710678118654752f));
}

__device__ __forceinline__ float tf32f(float x) {
    unsigned u;
    asm("cvt.rna.tf32.f32 %0, %1;" : "=r"(u) : "f"(x));
    return __uint_as_float(u);
}

__device__ __forceinline__ void cpa16(float* dst, const float* src) {
    unsigned d = (unsigned)__cvta_generic_to_shared(dst);
    asm volatile("cp.async.ca.shared.global [%0], [%1], 16;" :: "r"(d), "l"(src));
}
#define CP_COMMIT() asm volatile("cp.async.commit_group;")
#define CP_WAIT1()  asm volatile("cp.async.wait_group 1;")
#define CP_WAIT0()  asm volatile("cp.async.wait_group 0;")

__device__ __forceinline__ void mma8(float4& d, unsigned a0, unsigned a1,
                                     unsigned a2, unsigned a3,
                                     unsigned b0, unsigned b1) {
    asm volatile(
        "mma.sync.aligned.m16n8k8.row.col.f32.tf32.tf32.f32 "
        "{%0,%1,%2,%3},{%4,%5,%6,%7},{%8,%9},{%0,%1,%2,%3};"
        : "+f"(d.x), "+f"(d.y), "+f"(d.z), "+f"(d.w)
        : "r"(a0), "r"(a1), "r"(a2), "r"(a3), "r"(b0), "r"(b1));
}

__device__ __forceinline__ int spatial_of_row(int row) {
    int win = row >> 6, n = row & 63;
    int b = win >> 9, d = (win >> 6) & 7, h = (win >> 3) & 7, w = win & 7;
    int wd = n >> 4, wh = (n >> 2) & 3, ww = n & 3;
    int Z = d * 4 + wd, Y = h * 4 + wh, X = w * 4 + ww;
    return ((b * 32 + Z) * 32 + Y) * 32 + X;
}

// ============================================================
// K-1: one-off weight prep: tf32-round all GEMM weights + zero stripe
// ============================================================
__global__ __launch_bounds__(256) void k_wprep(
    const float* __restrict__ w1, const float* __restrict__ w2,
    const float* __restrict__ qw, const float* __restrict__ pw,
    const float* __restrict__ jw)
{
    int i = blockIdx.x * 256 + threadIdx.x;
    if (i < 55296) {
        int k = i / 288, c = i % 288;
        float v = (c < 96) ? w1[k * 96 + c] : w2[k * 192 + (c - 96)];
        g_pool[OF_WEMB + i] = tf32f(v);
    }
    if (i < 27648) g_pool[OF_WQKV + i] = tf32f(qw[i]);
    if (i < 36864) g_pool[OF_WPROJ + i] = tf32f(pw[i]);
    if (i < 18432) g_pool[OF_WPJ + i] = tf32f(jw[i]);
    if (i < 6144)  g_pool[OF_ZROW + i] = 0.f;
}

// ============================================================
// K0: precompute rel-pos bias table
// ============================================================
__global__ __launch_bounds__(256) void k_bias(const float* __restrict__ rpb)
{
    int hh = blockIdx.x;
    for (int p = threadIdx.x; p < 4096; p += 256) {
        int n = p >> 6, m = p & 63;
        int nd = n >> 4, nh = (n >> 2) & 3, nw = n & 3;
        int md = m >> 4, mh = (m >> 2) & 3, mw = m & 3;
        int idx = ((nd - md + 3) * 49 + (nh - mh + 3) * 7 + (nw - mw + 3)) * 6 + hh;
        g_pool[OF_BIAS + hh * 4096 + p] = rpb[idx];
    }
}

// ============================================================
// K1: embed GEMM, K-chunk 16 double-buffered
// ============================================================
__global__ __launch_bounds__(256) void k_embed(
    const float* __restrict__ x, const float* __restrict__ b1,
    const float* __restrict__ ga, const float* __restrict__ ba,
    const float* __restrict__ b2,
    const float* __restrict__ gc, const float* __restrict__ bc)
{
    extern __shared__ float sm[];
    float* sAb[2] = { sm, sm + 1280 };
    float* sWb[2] = { sm + 2560, sm + 2560 + 4736 };
    float (*sOut)[288] = (float(*)[288])sm;
    const float* wemb = g_pool + OF_WEMB;
    const int tid = threadIdx.x, warp = tid >> 5, lane = tid & 31;
    const int g = lane >> 2, t = lane & 3;
    const int wm = warp >> 2, wn = warp & 3;
    const int row0 = blockIdx.x * 64;
    const int mrow = wm * 32;
    const int ar = tid >> 2, ac = (tid & 3) * 4;

    float4 acc[2][9];
#pragma unroll
    for (int mt = 0; mt < 2; mt++)
#pragma unroll
        for (int j = 0; j < 9; j++) acc[mt][j] = make_float4(0.f, 0.f, 0.f, 0.f);

    {
        cpa16(sAb[0] + ar * 20 + ac, x + (size_t)(row0 + ar) * 192 + ac);
#pragma unroll
        for (int i = 0; i < 5; i++) {
            int idx = tid + i * 256;
            if (idx < 1152) {
                int r = idx / 72, c = (idx % 72) * 4;
                cpa16(sWb[0] + r * 296 + c, wemb + (size_t)r * 288 + c);
            }
        }
        CP_COMMIT();
    }

    for (int it = 0; it < 12; it++) {
        int buf = it & 1;
        if (it < 11) {
            int kb = (it + 1) * 16, nb = buf ^ 1;
            cpa16(sAb[nb] + ar * 20 + ac, x + (size_t)(row0 + ar) * 192 + kb + ac);
#pragma unroll
            for (int i = 0; i < 5; i++) {
                int idx = tid + i * 256;
                if (idx < 1152) {
                    int r = idx / 72, c = (idx % 72) * 4;
                    cpa16(sWb[nb] + r * 296 + c, wemb + (size_t)(kb + r) * 288 + c);
                }
            }
            CP_COMMIT();
            CP_WAIT1();
        } else {
            CP_WAIT0();
        }
        __syncthreads();
        const float* sA = sAb[buf];
        const float* sW = sWb[buf];
#pragma unroll
        for (int sk = 0; sk < 16; sk += 8) {
            unsigned a0[2], a1[2], a2[2], a3[2];
#pragma unroll
            for (int mt = 0; mt < 2; mt++) {
                int r = mrow + mt * 16;
                a0[mt] = __float_as_uint(tf32f(sA[(r + g) * 20 + sk + t]));
                a1[mt] = __float_as_uint(tf32f(sA[(r + g + 8) * 20 + sk + t]));
                a2[mt] = __float_as_uint(tf32f(sA[(r + g) * 20 + sk + t + 4]));
                a3[mt] = __float_as_uint(tf32f(sA[(r + g + 8) * 20 + sk + t + 4]));
            }
#pragma unroll
            for (int j = 0; j < 9; j++) {
                int n0 = wn * 72 + j * 8;
                unsigned b0v = __float_as_uint(sW[(sk + t) * 296 + n0 + g]);
                unsigned b1v = __float_as_uint(sW[(sk + t + 4) * 296 + n0 + g]);
                mma8(acc[0][j], a0[0], a1[0], a2[0], a3[0], b0v, b1v);
                mma8(acc[1][j], a0[1], a1[1], a2[1], a3[1], b0v, b1v);
            }
        }
        __syncthreads();
    }
#pragma unroll
    for (int mt = 0; mt < 2; mt++) {
        int r0 = mrow + mt * 16 + g, r1 = r0 + 8;
#pragma unroll
        for (int j = 0; j < 9; j++) {
            int c = wn * 72 + j * 8 + 2 * t;
            float bx = (c < 96) ? b1[c] : b2[c - 96];
            float by = (c + 1 < 96) ? b1[c + 1] : b2[c + 1 - 96];
            sOut[r0][c] = acc[mt][j].x + bx; sOut[r0][c + 1] = acc[mt][j].y + by;
            sOut[r1][c] = acc[mt][j].z + bx; sOut[r1][c + 1] = acc[mt][j].w + by;
        }
    }
    __syncthreads();

    for (int r = warp; r < 64; r += 8) {
        int row = row0 + r;
        float s = 0.f, q = 0.f;
#pragma unroll
        for (int i = 0; i < 3; i++) { float v = sOut[r][lane + 32 * i]; s += v; q += v * v; }
#pragma unroll
        for (int o = 16; o; o >>= 1) { s += __shfl_xor_sync(~0u, s, o); q += __shfl_xor_sync(~0u, q, o); }
        float m = s * (1.f / 96.f);
        float rs = rsqrtf(fmaxf(q * (1.f / 96.f) - m * m, 0.f) + EPS);
        float* xao = g_pool + OF_XATT + (size_t)row * 96;
#pragma unroll
        for (int i = 0; i < 3; i++) {
            int c = lane + 32 * i;
            xao[c] = tf32f((sOut[r][c] - m) * rs * ga[c] + ba[c]);
        }
        s = 0.f; q = 0.f;
#pragma unroll
        for (int i = 0; i < 6; i++) { float v = sOut[r][96 + lane + 32 * i]; s += v; q += v * v; }
#pragma unroll
        for (int o = 16; o; o >>= 1) { s += __shfl_xor_sync(~0u, s, o); q += __shfl_xor_sync(~0u, q, o); }
        m = s * (1.f / 192.f);
        rs = rsqrtf(fmaxf(q * (1.f / 192.f) - m * m, 0.f) + EPS);
        float* va = g_pool + OF_VOLA + (size_t)spatial_of_row(row) * 192;
#pragma unroll
        for (int i = 0; i < 6; i++) {
            int c = lane + 32 * i;
            va[c] = (sOut[r][96 + c] - m) * rs * gc[c] + bc[c];
        }
    }
}

// ============================================================
// K2: depthwise conv 3x3x3 + bias, partial stats
// zero-stripe for invalid (z,y), fully unrolled x-loop
// ============================================================
__global__ __launch_bounds__(192) void k_dwconv(
    const float* __restrict__ dww, const float* __restrict__ dwb)
{
    const float* vin = g_pool + OF_VOLA;
    float* vout = g_pool + OF_VOLB;
    int c = threadIdx.x;
    int blk = blockIdx.x;
    int b = blk >> 10, z = (blk >> 5) & 31, y = blk & 31;

    float w[27];
#pragma unroll
    for (int i = 0; i < 27; i++) w[i] = dww[c * 27 + i];
    float bias = dwb[c];

    const float* base[9];
#pragma unroll
    for (int dz = 0; dz < 3; dz++)
#pragma unroll
        for (int dy = 0; dy < 3; dy++) {
            int l = dz * 3 + dy;
            int zz = z + dz - 1, yy = y + dy - 1;
            bool ok = (zz >= 0 && zz < 32 && yy >= 0 && yy < 32);
            base[l] = ok ? (vin + ((size_t)((b * 32 + zz) * 32 + yy) * 32) * 192 + c)
                         : (g_pool + OF_ZROW + c);
        }
    float p0[9], p1[9];
#pragma unroll
    for (int l = 0; l < 9; l++) { p0[l] = 0.f; p1[l] = base[l][0]; }

    float ssum = 0.f, ssq = 0.f;
    float* orow = vout + ((size_t)blk * 32) * 192 + c;
#pragma unroll
    for (int xx = 0; xx < 32; xx++) {
        float p2[9];
        if (xx < 31) {
#pragma unroll
            for (int l = 0; l < 9; l++) p2[l] = base[l][(xx + 1) * 192];
        } else {
#pragma unroll
            for (int l = 0; l < 9; l++) p2[l] = 0.f;
        }
        float a = bias;
#pragma unroll
        for (int l = 0; l < 9; l++)
            a += w[l * 3 + 0] * p0[l] + w[l * 3 + 1] * p1[l] + w[l * 3 + 2] * p2[l];
        orow[xx * 192] = a;
        ssum += a; ssq += a * a;
#pragma unroll
        for (int l = 0; l < 9; l++) { p0[l] = p1[l]; p1[l] = p2[l]; }
    }
    g_pool[OF_PCS + (size_t)blk * 192 + c] = ssum;
    g_pool[OF_PCQ + (size_t)blk * 192 + c] = ssq;
}

// ============================================================
// reductions
// ============================================================
__global__ __launch_bounds__(128) void k_redstats(
    unsigned long long ofs, unsigned long long ofq, int nchunk, int C, float invN,
    unsigned long long ofm, unsigned long long ofr)
{
    __shared__ float ss[128], qq[128];
    int g = blockIdx.x; int b = g / C, c = g % C;
    float s = 0.f, q = 0.f;
    for (int i = threadIdx.x; i < nchunk; i += 128) {
        size_t o = ((size_t)b * nchunk + i) * C + c;
        s += g_pool[ofs + o]; q += g_pool[ofq + o];
    }
    ss[threadIdx.x] = s; qq[threadIdx.x] = q; __syncthreads();
    for (int o = 64; o; o >>= 1) {
        if (threadIdx.x < o) { ss[threadIdx.x] += ss[threadIdx.x + o]; qq[threadIdx.x] += qq[threadIdx.x + o]; }
        __syncthreads();
    }
    if (threadIdx.x == 0) {
        float m = ss[0] * invN;
        g_pool[ofm + g] = m;
        g_pool[ofr + g] = rsqrtf(fmaxf(qq[0] * invN - m * m, 0.f) + EPS);
    }
}

__global__ __launch_bounds__(128) void k_redmean(
    unsigned long long ofs, int nchunk, int C, float invN, unsigned long long ofm)
{
    __shared__ float ss[128];
    int g = blockIdx.x; int b = g / C, c = g % C;
    float s = 0.f;
    for (int i = threadIdx.x; i < nchunk; i += 128)
        s += g_pool[ofs + ((size_t)b * nchunk + i) * C + c];
    ss[threadIdx.x] = s; __syncthreads();
    for (int o = 64; o; o >>= 1) {
        if (threadIdx.x < o) ss[threadIdx.x] += ss[threadIdx.x + o];
        __syncthreads();
    }
    if (threadIdx.x == 0) g_pool[ofm + g] = ss[0] * invN;
}

// ============================================================
// K4: pooled partials only
// ============================================================
__global__ __launch_bounds__(192) void k_pool()
{
    int c = threadIdx.x;
    int blk = blockIdx.x; int b = blk >> 10;
    float m = g_pool[OF_M1 + b * 192 + c], rs = g_pool[OF_R1 + b * 192 + c];
    const float* v = g_pool + OF_VOLB + ((size_t)blk * 32) * 192 + c;
    float s = 0.f;
    for (int xx = 0; xx < 32; xx++)
        s += geluf((v[(size_t)xx * 192] - m) * rs);
    g_pool[OF_PPOOL + (size_t)blk * 192 + c] = s;
}

// ============================================================
// K5: ci MLP
// ============================================================
__global__ __launch_bounds__(96) void k_ci(
    const float* __restrict__ w1, const float* __restrict__ b1,
    const float* __restrict__ w2, const float* __restrict__ b2, int nb)
{
    __shared__ float t24[24];
    int tid = threadIdx.x;
    for (int b = 0; b < nb; b++) {
        if (tid < 24) {
            float s = b1[tid];
            for (int c = 0; c < 192; c++) s += g_pool[OF_POOLED + b * 192 + c] * w1[c * 24 + tid];
            t24[tid] = geluf(s);
        }
        __syncthreads();
        {
            float s = b2[tid];
#pragma unroll
            for (int j = 0; j < 24; j++) s += t24[j] * w2[j * 96 + tid];
            g_pool[OF_GATE + b * 96 + tid] = 1.f / (1.f + expf(-s));
        }
        __syncthreads();
    }
}

// ============================================================
// K6: pj conv1x1 (pre-tf32 W, fused inorm+gelu A)
// ============================================================
__global__ __launch_bounds__(256) void k_pj(const float* __restrict__ pb)
{
    __shared__ float sA[64][36];
    __shared__ float sW[32][104];
    const int tid = threadIdx.x, warp = tid >> 5, lane = tid & 31;
    const int g = lane >> 2, t = lane & 3;
    const int wm = warp >> 2, wn = warp & 3;
    const int row0 = blockIdx.x * 64;
    const int b = row0 >> 15;
    const int mrow = wm * 32;
    const float* vb = g_pool + OF_VOLB;
    const float* wpj = g_pool + OF_WPJ;
    const float* M1 = g_pool + OF_M1 + b * 192;
    const float* R1 = g_pool + OF_R1 + b * 192;

    float4 acc[2][3];
#pragma unroll
    for (int mt = 0; mt < 2; mt++)
#pragma unroll
        for (int j = 0; j < 3; j++) acc[mt][j] = make_float4(0.f, 0.f, 0.f, 0.f);

    for (int kb = 0; kb < 192; kb += 32) {
#pragma unroll
        for (int i = 0; i < 2; i++) {
            int idx = tid * 2 + i; int r = idx >> 3, c = (idx & 7) * 4;
            float4 v = *(const float4*)(vb + (size_t)spatial_of_row(row0 + r) * 192 + kb + c);
            int ch = kb + c;
            sA[r][c]     = tf32f(geluf((v.x - M1[ch])     * R1[ch]));
            sA[r][c + 1] = tf32f(geluf((v.y - M1[ch + 1]) * R1[ch + 1]));
            sA[r][c + 2] = tf32f(geluf((v.z - M1[ch + 2]) * R1[ch + 2]));
            sA[r][c + 3] = tf32f(geluf((v.w - M1[ch + 3]) * R1[ch + 3]));
        }
#pragma unroll
        for (int i = 0; i < 3; i++) {
            int idx = tid + i * 256; int r = idx / 24, c = (idx % 24) * 4;
            *(float4*)&sW[r][c] = *(const float4*)(wpj + (size_t)(kb + r) * 96 + c);
        }
        __syncthreads();
#pragma unroll
        for (int sk = 0; sk < 32; sk += 8) {
            unsigned a0[2], a1[2], a2[2], a3[2];
#pragma unroll
            for (int mt = 0; mt < 2; mt++) {
                int r = mrow + mt * 16;
                a0[mt] = __float_as_uint(sA[r + g][sk + t]);
                a1[mt] = __float_as_uint(sA[r + g + 8][sk + t]);
                a2[mt] = __float_as_uint(sA[r + g][sk + t + 4]);
                a3[mt] = __float_as_uint(sA[r + g + 8][sk + t + 4]);
            }
#pragma unroll
            for (int j = 0; j < 3; j++) {
                int n0 = wn * 24 + j * 8;
                unsigned b0v = __float_as_uint(sW[sk + t][n0 + g]);
                unsigned b1v = __float_as_uint(sW[sk + t + 4][n0 + g]);
                mma8(acc[0][j], a0[0], a1[0], a2[0], a3[0], b0v, b1v);
                mma8(acc[1][j], a0[1], a1[1], a2[1], a3[1], b0v, b1v);
            }
        }
        __syncthreads();
    }
    float* vp = g_pool + OF_VOLP;
#pragma unroll
    for (int mt = 0; mt < 2; mt++) {
        int r0 = row0 + mrow + mt * 16 + g, r1 = r0 + 8;
#pragma unroll
        for (int j = 0; j < 3; j++) {
            int c = wn * 24 + j * 8 + 2 * t;
            float bx = pb[c], by = pb[c + 1];
            *(float2*)&vp[(size_t)r0 * 96 + c] = make_float2(acc[mt][j].x + bx, acc[mt][j].y + by);
            *(float2*)&vp[(size_t)r1 * 96 + c] = make_float2(acc[mt][j].z + bx, acc[mt][j].w + by);
        }
    }
}

// ============================================================
// K7a: qkv GEMM, K-chunk 16 double-buffered
// ============================================================
__global__ __launch_bounds__(256) void k_qkv(const float* __restrict__ qb)
{
    extern __shared__ float sm[];
    float* sAb[2] = { sm, sm + 1280 };
    float* sWb[2] = { sm + 2560, sm + 2560 + 4736 };
    const float* A = g_pool + OF_XATT;
    const float* wq = g_pool + OF_WQKV;
    const int tid = threadIdx.x, warp = tid >> 5, lane = tid & 31;
    const int g = lane >> 2, t = lane & 3;
    const int wm = warp >> 2, wn = warp & 3;
    const int row0 = blockIdx.x * 64;
    const int mrow = wm * 32;
    const int ar = tid >> 2, ac = (tid & 3) * 4;

    float4 acc[2][9];
#pragma unroll
    for (int mt = 0; mt < 2; mt++)
#pragma unroll
        for (int j = 0; j < 9; j++) acc[mt][j] = make_float4(0.f, 0.f, 0.f, 0.f);

    {
        cpa16(sAb[0] + ar * 20 + ac, A + (size_t)(row0 + ar) * 96 + ac);
#pragma unroll
        for (int i = 0; i < 5; i++) {
            int idx = tid + i * 256;
            if (idx < 1152) {
                int r = idx / 72, c = (idx % 72) * 4;
                cpa16(sWb[0] + r * 296 + c, wq + (size_t)r * 288 + c);
            }
        }
        CP_COMMIT();
    }

    for (int it = 0; it < 6; it++) {
        int buf = it & 1;
        if (it < 5) {
            int kb = (it + 1) * 16, nb = buf ^ 1;
            cpa16(sAb[nb] + ar * 20 + ac, A + (size_t)(row0 + ar) * 96 + kb + ac);
#pragma unroll
            for (int i = 0; i < 5; i++) {
                int idx = tid + i * 256;
                if (idx < 1152) {
                    int r = idx / 72, c = (idx % 72) * 4;
                    cpa16(sWb[nb] + r * 296 + c, wq + (size_t)(kb + r) * 288 + c);
                }
            }
            CP_COMMIT();
            CP_WAIT1();
        } else {
            CP_WAIT0();
        }
        __syncthreads();
        const float* sA = sAb[buf];
        const float* sW = sWb[buf];
#pragma unroll
        for (int sk = 0; sk < 16; sk += 8) {
            unsigned a0[2], a1[2], a2[2], a3[2];
#pragma unroll
            for (int mt = 0; mt < 2; mt++) {
                int r = mrow + mt * 16;
                a0[mt] = __float_as_uint(sA[(r + g) * 20 + sk + t]);
                a1[mt] = __float_as_uint(sA[(r + g + 8) * 20 + sk + t]);
                a2[mt] = __float_as_uint(sA[(r + g) * 20 + sk + t + 4]);
                a3[mt] = __float_as_uint(sA[(r + g + 8) * 20 + sk + t + 4]);
            }
#pragma unroll
            for (int j = 0; j < 9; j++) {
                int n0 = wn * 72 + j * 8;
                unsigned b0v = __float_as_uint(sW[(sk + t) * 296 + n0 + g]);
                unsigned b1v = __float_as_uint(sW[(sk + t + 4) * 296 + n0 + g]);
                mma8(acc[0][j], a0[0], a1[0], a2[0], a3[0], b0v, b1v);
                mma8(acc[1][j], a0[1], a1[1], a2[1], a3[1], b0v, b1v);
            }
        }
        __syncthreads();
    }
    float* Q = g_pool + OF_QKV + (size_t)blockIdx.x * 18432;
    const float* gate = g_pool + OF_GATE + (blockIdx.x >> 9) * 96;
#pragma unroll
    for (int mt = 0; mt < 2; mt++) {
        int n0r = mrow + mt * 16 + g, n1r = n0r + 8;
#pragma unroll
        for (int j = 0; j < 9; j++) {
            int c = wn * 72 + j * 8 + 2 * t;
            int s = c / 96, rem = c - s * 96, h = rem >> 4, d = rem & 15;
            float bx = qb[c], by = qb[c + 1];
            float x0 = acc[mt][j].x + bx, y0 = acc[mt][j].y + by;
            float z0 = acc[mt][j].z + bx, w0 = acc[mt][j].w + by;
            if (s == 0) { x0 *= 0.25f; y0 *= 0.25f; z0 *= 0.25f; w0 *= 0.25f; }
            else if (s == 2) {
                float g0 = gate[rem], g1 = gate[rem + 1];
                x0 *= g0; y0 *= g1; z0 *= g0; w0 *= g1;
            }
            float* dst = Q + s * 6144 + h * 1024 + d;
            *(float2*)(dst + n0r * 16) = make_float2(x0, y0);
            *(float2*)(dst + n1r * 16) = make_float2(z0, w0);
        }
    }
}

// ============================================================
// K7b: attention per window (vectorized smem, pad 20)
// ============================================================
__global__ __launch_bounds__(256) void k_attn()
{
    __shared__ float qS[64][20], kS[64][20], vS[64][20];
    __shared__ float pS[64][65];
    int tid = threadIdx.x;
    int win = blockIdx.x;
    const float* qkv = g_pool + OF_QKV + (size_t)win * 18432;
    const float* biasT = g_pool + OF_BIAS;
    float* out = g_pool + OF_AOUT + (size_t)win * 64 * 96;
    int warp = tid >> 5, lane = tid & 31;
    int sn = tid >> 2, sd = (tid & 3) * 4;

    for (int hh = 0; hh < 6; hh++) {
        {
            const float* base = qkv + hh * 1024 + sn * 16 + sd;
            *(float4*)&qS[sn][sd] = *(const float4*)(base);
            *(float4*)&kS[sn][sd] = *(const float4*)(base + 6144);
            *(float4*)&vS[sn][sd] = *(const float4*)(base + 12288);
        }
        __syncthreads();
        for (int rr = 0; rr < 8; rr++) {
            int n = warp * 8 + rr;
            int m0 = lane, m1 = lane + 32;
            float s0 = biasT[hh * 4096 + n * 64 + m0];
            float s1 = biasT[hh * 4096 + n * 64 + m1];
#pragma unroll
            for (int d4 = 0; d4 < 4; d4++) {
                float4 qv = *(const float4*)&qS[n][d4 * 4];
                float4 k0 = *(const float4*)&kS[m0][d4 * 4];
                float4 k1 = *(const float4*)&kS[m1][d4 * 4];
                s0 += qv.x * k0.x + qv.y * k0.y + qv.z * k0.z + qv.w * k0.w;
                s1 += qv.x * k1.x + qv.y * k1.y + qv.z * k1.z + qv.w * k1.w;
            }
            float mx = fmaxf(s0, s1);
#pragma unroll
            for (int o = 16; o; o >>= 1) mx = fmaxf(mx, __shfl_xor_sync(~0u, mx, o));
            float e0 = expf(s0 - mx), e1 = expf(s1 - mx);
            float sum = e0 + e1;
#pragma unroll
            for (int o = 16; o; o >>= 1) sum += __shfl_xor_sync(~0u, sum, o);
            float inv = 1.f / sum;
            pS[n][m0] = e0 * inv;
            pS[n][m1] = e1 * inv;
        }
        __syncthreads();
        {
            int n = tid >> 2, dg = tid & 3;
            float a0 = 0.f, a1 = 0.f, a2 = 0.f, a3 = 0.f;
#pragma unroll
            for (int m = 0; m < 64; m++) {
                float pm = pS[n][m];
                float4 v = *(const float4*)&vS[m][dg * 4];
                a0 += pm * v.x; a1 += pm * v.y; a2 += pm * v.z; a3 += pm * v.w;
            }
            size_t ob = (size_t)n * 96 + hh * 16 + dg * 4;
            *(float4*)(out + ob) = make_float4(a0, a1, a2, a3);
        }
        __syncthreads();
    }
}

// ============================================================
// K8a: si stage 1
// ============================================================
__global__ __launch_bounds__(256) void k_si1(
    const float* __restrict__ w1, const float* __restrict__ b1)
{
    __shared__ float aS[64][97];
    __shared__ float wS[96 * 12];
    __shared__ float sb[64][12];
    int tid = threadIdx.x;
    int blk = blockIdx.x; int row0 = blk * 64;
    const float* A = g_pool + OF_AOUT;
    for (int i = tid; i < 96 * 12; i += 256) wS[i] = w1[i];
    for (int i = tid; i < 64 * 96; i += 256) {
        int r = i / 96, c = i % 96;
        aS[r][c] = A[(size_t)(row0 + r) * 96 + c];
    }
    __syncthreads();
    {
        int r = tid >> 2, jg = tid & 3;
        float s0 = b1[jg * 3 + 0], s1 = b1[jg * 3 + 1], s2 = b1[jg * 3 + 2];
        for (int c = 0; c < 96; c++) {
            float a = aS[r][c];
            s0 += a * wS[c * 12 + jg * 3 + 0];
            s1 += a * wS[c * 12 + jg * 3 + 1];
            s2 += a * wS[c * 12 + jg * 3 + 2];
        }
        float* o = g_pool + OF_S12 + (size_t)(row0 + r) * 12 + jg * 3;
        o[0] = s0; o[1] = s1; o[2] = s2;
        sb[r][jg * 3 + 0] = s0; sb[r][jg * 3 + 1] = s1; sb[r][jg * 3 + 2] = s2;
    }
    __syncthreads();
    if (tid < 12) {
        float S = 0.f, Q = 0.f;
        for (int r = 0; r < 64; r++) { float v = sb[r][tid]; S += v; Q += v * v; }
        g_pool[OF_P12S + (size_t)blk * 12 + tid] = S;
        g_pool[OF_P12Q + (size_t)blk * 12 + tid] = Q;
    }
}

// ============================================================
// K8c: gate + multiply + partials
// ============================================================
__global__ __launch_bounds__(96) void k_gatemul(
    const float* __restrict__ w2, const float* __restrict__ b2)
{
    __shared__ float gb[64];
    int tid = threadIdx.x;
    int blk = blockIdx.x; int row0 = blk * 64; int b = row0 >> 15;
    if (tid < 64) {
        const float* s = g_pool + OF_S12 + (size_t)(row0 + tid) * 12;
        float a = b2[0];
#pragma unroll
        for (int j = 0; j < 12; j++) {
            float v = (s[j] - g_pool[OF_M2 + b * 12 + j]) * g_pool[OF_R2 + b * 12 + j];
            a += geluf(v) * w2[j];
        }
        gb[tid] = 1.f / (1.f + expf(-a));
    }
    __syncthreads();
    const float* vp = g_pool + OF_VOLP + (size_t)row0 * 96 + tid;
    float* yv = g_pool + OF_YV + (size_t)row0 * 96 + tid;
    float ss = 0.f, sq = 0.f;
    for (int r = 0; r < 64; r++) {
        float y = gb[r] * vp[(size_t)r * 96];
        yv[(size_t)r * 96] = y;
        ss += y; sq += y * y;
    }
    g_pool[OF_PYS + (size_t)blk * 96 + tid] = ss;
    g_pool[OF_PYQ + (size_t)blk * 96 + tid] = sq;
}

// ============================================================
// K9: final (tf32 mma, K-chunk 16 double-buffered W, 3 CTA/SM)
// ============================================================
__global__ __launch_bounds__(256, 3) void k_final(
    const float* __restrict__ bp,
    const float* __restrict__ ga, const float* __restrict__ ba,
    float* __restrict__ out)
{
    extern __shared__ float sm[];
    float (*sA)[196] = (float(*)[196])sm;
    float* sWb[2] = { sm + 12544, sm + 12544 + 3200 };
    const float* wp = g_pool + OF_WPROJ;
    const int tid = threadIdx.x, warp = tid >> 5, lane = tid & 31;
    const int g = lane >> 2, t = lane & 3;
    const int wm = warp >> 2, wn = warp & 3;
    const int row0 = blockIdx.x * 64; const int b = row0 >> 15;
    const int mrow = wm * 32;
    const float* A = g_pool + OF_AOUT;
    const float* Y = g_pool + OF_YV;

    {
#pragma unroll
        for (int i = 0; i < 3; i++) {
            int idx = tid + i * 256; int r = idx / 48, c = (idx % 48) * 4;
            cpa16(sWb[0] + r * 200 + c, wp + (size_t)r * 192 + c);
        }
        CP_COMMIT();
    }

    for (int it = 0; it < 8; it++) {
        int r = warp * 8 + it;
        int row = row0 + r;
        float s = 0.f, q = 0.f;
        float vals[3];
#pragma unroll
        for (int i = 0; i < 3; i++) {
            vals[i] = A[(size_t)row * 96 + lane + 32 * i];
            s += vals[i]; q += vals[i] * vals[i];
        }
#pragma unroll
        for (int o = 16; o; o >>= 1) { s += __shfl_xor_sync(~0u, s, o); q += __shfl_xor_sync(~0u, q, o); }
        float m = s * (1.f / 96.f);
        float rs = rsqrtf(fmaxf(q * (1.f / 96.f) - m * m, 0.f) + EPS);
#pragma unroll
        for (int i = 0; i < 3; i++) {
            int c = lane + 32 * i;
            sA[r][c] = tf32f((vals[i] - m) * rs * ga[c] + ba[c]);
        }
#pragma unroll
        for (int i = 0; i < 3; i++) {
            int c = lane + 32 * i;
            float v = (Y[(size_t)row * 96 + c] - g_pool[OF_M3 + b * 96 + c]) * g_pool[OF_R3 + b * 96 + c];
            sA[r][96 + c] = tf32f(v);
        }
    }
    __syncthreads();

    float4 acc[2][6];
#pragma unroll
    for (int mt = 0; mt < 2; mt++)
#pragma unroll
        for (int j = 0; j < 6; j++) acc[mt][j] = make_float4(0.f, 0.f, 0.f, 0.f);

    for (int it = 0; it < 12; it++) {
        int buf = it & 1;
        int kb = it * 16;
        if (it < 11) {
            int nkb = kb + 16, nb = buf ^ 1;
#pragma unroll
            for (int i = 0; i < 3; i++) {
                int idx = tid + i * 256; int r = idx / 48, c = (idx % 48) * 4;
                cpa16(sWb[nb] + r * 200 + c, wp + (size_t)(nkb + r) * 192 + c);
            }
            CP_COMMIT();
            CP_WAIT1();
        } else {
            CP_WAIT0();
        }
        __syncthreads();
        const float* sW = sWb[buf];
#pragma unroll
        for (int sk = 0; sk < 16; sk += 8) {
            unsigned a0[2], a1[2], a2[2], a3[2];
#pragma unroll
            for (int mt = 0; mt < 2; mt++) {
                int r = mrow + mt * 16;
                a0[mt] = __float_as_uint(sA[r + g][kb + sk + t]);
                a1[mt] = __float_as_uint(sA[r + g + 8][kb + sk + t]);
                a2[mt] = __float_as_uint(sA[r + g][kb + sk + t + 4]);
                a3[mt] = __float_as_uint(sA[r + g + 8][kb + sk + t + 4]);
            }
#pragma unroll
            for (int j = 0; j < 6; j++) {
                int n0 = wn * 48 + j * 8;
                unsigned b0v = __float_as_uint(sW[(sk + t) * 200 + n0 + g]);
                unsigned b1v = __float_as_uint(sW[(sk + t + 4) * 200 + n0 + g]);
                mma8(acc[0][j], a0[0], a1[0], a2[0], a3[0], b0v, b1v);
                mma8(acc[1][j], a0[1], a1[1], a2[1], a3[1], b0v, b1v);
            }
        }
        __syncthreads();
    }
#pragma unroll
    for (int mt = 0; mt < 2; mt++) {
        int r0 = row0 + mrow + mt * 16 + g, r1 = r0 + 8;
#pragma unroll
        for (int j = 0; j < 6; j++) {
            int c = wn * 48 + j * 8 + 2 * t;
            float bx = bp[c], by = bp[c + 1];
            *(float2*)&out[(size_t)r0 * 192 + c] = make_float2(acc[mt][j].x + bx, acc[mt][j].y + by);
            *(float2*)&out[(size_t)r1 * 192 + c] = make_float2(acc[mt][j].z + bx, acc[mt][j].w + by);
        }
    }
}

// ============================================================
// host launcher
// ============================================================
extern "C" void kernel_launch(void* const* d_in, const int* in_sizes, int n_in,
                              void* d_out, int out_size)
{
    const float* x       = (const float*)d_in[0];
    const float* w_pattn = (const float*)d_in[1];
    const float* b_pattn = (const float*)d_in[2];
    const float* g_aln   = (const float*)d_in[3];
    const float* b_aln   = (const float*)d_in[4];
    const float* w_pcnn  = (const float*)d_in[5];
    const float* b_pcnn  = (const float*)d_in[6];
    const float* g_cln   = (const float*)d_in[7];
    const float* b_cln   = (const float*)d_in[8];
    const float* dw_w    = (const float*)d_in[9];
    const float* dw_b    = (const float*)d_in[10];
    const float* ci_w1   = (const float*)d_in[11];
    const float* ci_b1   = (const float*)d_in[12];
    const float* ci_w2   = (const float*)d_in[13];
    const float* ci_b2   = (const float*)d_in[14];
    const float* pj_w    = (const float*)d_in[15];
    const float* pj_b    = (const float*)d_in[16];
    const float* qkv_w   = (const float*)d_in[17];
    const float* qkv_b   = (const float*)d_in[18];
    const float* si_w1   = (const float*)d_in[19];
    const float* si_b1   = (const float*)d_in[20];
    const float* si_w2   = (const float*)d_in[21];
    const float* si_b2   = (const float*)d_in[22];
    const float* g_anorm = (const float*)d_in[23];
    const float* b_anorm = (const float*)d_in[24];
    const float* w_proj  = (const float*)d_in[25];
    const float* b_proj  = (const float*)d_in[26];
    const float* rpb     = (const float*)d_in[27];

    const int Bwin = in_sizes[0] / (64 * 192);   // 2048
    const int rows = Bwin * 64;                  // 131072
    const int nb   = Bwin / 512;                 // 4

    cudaFuncSetAttribute(k_embed, cudaFuncAttributeMaxDynamicSharedMemorySize, 75776);
    cudaFuncSetAttribute(k_qkv,   cudaFuncAttributeMaxDynamicSharedMemorySize, 50176);
    cudaFuncSetAttribute(k_final, cudaFuncAttributeMaxDynamicSharedMemorySize, 77824);

    // k_dwconv at launch index 3 (ncu capture slot)
    k_wprep<<<216, 256>>>(w_pattn, w_pcnn, qkv_w, w_proj, pj_w);
    k_bias<<<6, 256>>>(rpb);
    k_embed<<<rows / 64, 256, 73728>>>(x, b_pattn, g_aln, b_aln,
                                       b_pcnn, g_cln, b_cln);
    k_dwconv<<<nb * 1024, 192>>>(dw_w, dw_b);
    k_redstats<<<nb * 192, 128>>>(OF_PCS, OF_PCQ, 1024, 192, 1.f / 32768.f, OF_M1, OF_R1);
    k_pool<<<nb * 1024, 192>>>();
    k_redmean<<<nb * 192, 128>>>(OF_PPOOL, 1024, 192, 1.f / 32768.f, OF_POOLED);
    k_ci<<<1, 96>>>(ci_w1, ci_b1, ci_w2, ci_b2, nb);
    k_pj<<<rows / 64, 256>>>(pj_b);
    k_qkv<<<rows / 64, 256, 48128>>>(qkv_b);
    k_attn<<<Bwin, 256>>>();
    k_si1<<<rows / 64, 256>>>(si_w1, si_b1);
    k_redstats<<<nb * 12, 128>>>(OF_P12S, OF_P12Q, 512, 12, 1.f / 32768.f, OF_M2, OF_R2);
    k_gatemul<<<rows / 64, 96>>>(si_w2, si_b2);
    k_redstats<<<nb * 96, 128>>>(OF_PYS, OF_PYQ, 512, 96, 1.f / 32768.f, OF_M3, OF_R3);
    k_final<<<rows / 64, 256, 75776>>>(b_proj, g_anorm, b_anorm, (float*)d_out);
}

// round 15
// speedup vs baseline: 1.0359x; 1.0359x over previous
#include <cuda_runtime.h>
#include <math.h>

#define EPS 1e-5f

// ---------------- scratch pool (floats) ----------------
#define OF_VOLA   0ull
#define OF_VOLB   25165824ull
#define OF_QKV    50331648ull
#define OF_XATT   88080384ull
#define OF_AOUT   100663296ull
#define OF_VOLP   113246208ull
#define OF_YV     125829120ull
#define OF_S12    138412032ull
#define OF_PCS    139984896ull
#define OF_PCQ    140771328ull
#define OF_PPOOL  141557760ull
#define OF_P12S   142344192ull
#define OF_P12Q   142368768ull
#define OF_PYS    142393344ull
#define OF_PYQ    142589952ull
#define OF_M1     142786560ull
#define OF_R1     142787328ull
#define OF_POOLED 142788096ull
#define OF_M2     142788864ull
#define OF_R2     142788912ull
#define OF_M3     142788960ull
#define OF_R3     142789344ull
#define OF_GATE   142789728ull
#define OF_BIAS   142790144ull   // 24576
#define OF_WEMB   142814720ull   // 192*288 = 55296
#define OF_WQKV   142870016ull   // 96*288  = 27648
#define OF_WPROJ  142897664ull   // 192*192 = 36864
#define OF_WPJ    142934528ull   // 192*96  = 18432
#define OF_ZROW   142952960ull   // 6144 zeros (32*192)

__device__ float g_pool[143000000];

__device__ __forceinline__ float geluf(float x) {
    return 0.5f * x * (1.0f + erff(x * 0.70710678118654752f));
}

__device__ __forceinline__ float tf32f(float x) {
    unsigned u;
    asm("cvt.rna.tf32.f32 %0, %1;" : "=r"(u) : "f"(x));
    return __uint_as_float(u);
}

__device__ __forceinline__ void cpa16(float* dst, const float* src) {
    unsigned d = (unsigned)__cvta_generic_to_shared(dst);
    asm volatile("cp.async.ca.shared.global [%0], [%1], 16;" :: "r"(d), "l"(src));
}
#define CP_COMMIT() asm volatile("cp.async.commit_group;")
#define CP_WAIT1()  asm volatile("cp.async.wait_group 1;")
#define CP_WAIT0()  asm volatile("cp.async.wait_group 0;")

__device__ __forceinline__ void mma8(float4& d, unsigned a0, unsigned a1,
                                     unsigned a2, unsigned a3,
                                     unsigned b0, unsigned b1) {
    asm volatile(
        "mma.sync.aligned.m16n8k8.row.col.f32.tf32.tf32.f32 "
        "{%0,%1,%2,%3},{%4,%5,%6,%7},{%8,%9},{%0,%1,%2,%3};"
        : "+f"(d.x), "+f"(d.y), "+f"(d.z), "+f"(d.w)
        : "r"(a0), "r"(a1), "r"(a2), "r"(a3), "r"(b0), "r"(b1));
}

__device__ __forceinline__ int spatial_of_row(int row) {
    int win = row >> 6, n = row & 63;
    int b = win >> 9, d = (win >> 6) & 7, h = (win >> 3) & 7, w = win & 7;
    int wd = n >> 4, wh = (n >> 2) & 3, ww = n & 3;
    int Z = d * 4 + wd, Y = h * 4 + wh, X = w * 4 + ww;
    return ((b * 32 + Z) * 32 + Y) * 32 + X;
}

// ============================================================
// K-1: one-off weight prep: tf32-round all GEMM weights + zero stripe
// ============================================================
__global__ __launch_bounds__(256) void k_wprep(
    const float* __restrict__ w1, const float* __restrict__ w2,
    const float* __restrict__ qw, const float* __restrict__ pw,
    const float* __restrict__ jw)
{
    int i = blockIdx.x * 256 + threadIdx.x;
    if (i < 55296) {
        int k = i / 288, c = i % 288;
        float v = (c < 96) ? w1[k * 96 + c] : w2[k * 192 + (c - 96)];
        g_pool[OF_WEMB + i] = tf32f(v);
    }
    if (i < 27648) g_pool[OF_WQKV + i] = tf32f(qw[i]);
    if (i < 36864) g_pool[OF_WPROJ + i] = tf32f(pw[i]);
    if (i < 18432) g_pool[OF_WPJ + i] = tf32f(jw[i]);
    if (i < 6144)  g_pool[OF_ZROW + i] = 0.f;
}

// ============================================================
// K0: precompute rel-pos bias table
// ============================================================
__global__ __launch_bounds__(256) void k_bias(const float* __restrict__ rpb)
{
    int hh = blockIdx.x;
    for (int p = threadIdx.x; p < 4096; p += 256) {
        int n = p >> 6, m = p & 63;
        int nd = n >> 4, nh = (n >> 2) & 3, nw = n & 3;
        int md = m >> 4, mh = (m >> 2) & 3, mw = m & 3;
        int idx = ((nd - md + 3) * 49 + (nh - mh + 3) * 7 + (nw - mw + 3)) * 6 + hh;
        g_pool[OF_BIAS + hh * 4096 + p] = rpb[idx];
    }
}

// ============================================================
// K1: embed GEMM, K-chunk 16 double-buffered
// ============================================================
__global__ __launch_bounds__(256) void k_embed(
    const float* __restrict__ x, const float* __restrict__ b1,
    const float* __restrict__ ga, const float* __restrict__ ba,
    const float* __restrict__ b2,
    const float* __restrict__ gc, const float* __restrict__ bc)
{
    extern __shared__ float sm[];
    float* sAb[2] = { sm, sm + 1280 };
    float* sWb[2] = { sm + 2560, sm + 2560 + 4736 };
    float (*sOut)[288] = (float(*)[288])sm;
    const float* wemb = g_pool + OF_WEMB;
    const int tid = threadIdx.x, warp = tid >> 5, lane = tid & 31;
    const int g = lane >> 2, t = lane & 3;
    const int wm = warp >> 2, wn = warp & 3;
    const int row0 = blockIdx.x * 64;
    const int mrow = wm * 32;
    const int ar = tid >> 2, ac = (tid & 3) * 4;

    float4 acc[2][9];
#pragma unroll
    for (int mt = 0; mt < 2; mt++)
#pragma unroll
        for (int j = 0; j < 9; j++) acc[mt][j] = make_float4(0.f, 0.f, 0.f, 0.f);

    {
        cpa16(sAb[0] + ar * 20 + ac, x + (size_t)(row0 + ar) * 192 + ac);
#pragma unroll
        for (int i = 0; i < 5; i++) {
            int idx = tid + i * 256;
            if (idx < 1152) {
                int r = idx / 72, c = (idx % 72) * 4;
                cpa16(sWb[0] + r * 296 + c, wemb + (size_t)r * 288 + c);
            }
        }
        CP_COMMIT();
    }

    for (int it = 0; it < 12; it++) {
        int buf = it & 1;
        if (it < 11) {
            int kb = (it + 1) * 16, nb = buf ^ 1;
            cpa16(sAb[nb] + ar * 20 + ac, x + (size_t)(row0 + ar) * 192 + kb + ac);
#pragma unroll
            for (int i = 0; i < 5; i++) {
                int idx = tid + i * 256;
                if (idx < 1152) {
                    int r = idx / 72, c = (idx % 72) * 4;
                    cpa16(sWb[nb] + r * 296 + c, wemb + (size_t)(kb + r) * 288 + c);
                }
            }
            CP_COMMIT();
            CP_WAIT1();
        } else {
            CP_WAIT0();
        }
        __syncthreads();
        const float* sA = sAb[buf];
        const float* sW = sWb[buf];
#pragma unroll
        for (int sk = 0; sk < 16; sk += 8) {
            unsigned a0[2], a1[2], a2[2], a3[2];
#pragma unroll
            for (int mt = 0; mt < 2; mt++) {
                int r = mrow + mt * 16;
                a0[mt] = __float_as_uint(tf32f(sA[(r + g) * 20 + sk + t]));
                a1[mt] = __float_as_uint(tf32f(sA[(r + g + 8) * 20 + sk + t]));
                a2[mt] = __float_as_uint(tf32f(sA[(r + g) * 20 + sk + t + 4]));
                a3[mt] = __float_as_uint(tf32f(sA[(r + g + 8) * 20 + sk + t + 4]));
            }
#pragma unroll
            for (int j = 0; j < 9; j++) {
                int n0 = wn * 72 + j * 8;
                unsigned b0v = __float_as_uint(sW[(sk + t) * 296 + n0 + g]);
                unsigned b1v = __float_as_uint(sW[(sk + t + 4) * 296 + n0 + g]);
                mma8(acc[0][j], a0[0], a1[0], a2[0], a3[0], b0v, b1v);
                mma8(acc[1][j], a0[1], a1[1], a2[1], a3[1], b0v, b1v);
            }
        }
        __syncthreads();
    }
#pragma unroll
    for (int mt = 0; mt < 2; mt++) {
        int r0 = mrow + mt * 16 + g, r1 = r0 + 8;
#pragma unroll
        for (int j = 0; j < 9; j++) {
            int c = wn * 72 + j * 8 + 2 * t;
            float bx = (c < 96) ? b1[c] : b2[c - 96];
            float by = (c + 1 < 96) ? b1[c + 1] : b2[c + 1 - 96];
            sOut[r0][c] = acc[mt][j].x + bx; sOut[r0][c + 1] = acc[mt][j].y + by;
            sOut[r1][c] = acc[mt][j].z + bx; sOut[r1][c + 1] = acc[mt][j].w + by;
        }
    }
    __syncthreads();

    for (int r = warp; r < 64; r += 8) {
        int row = row0 + r;
        float s = 0.f, q = 0.f;
#pragma unroll
        for (int i = 0; i < 3; i++) { float v = sOut[r][lane + 32 * i]; s += v; q += v * v; }
#pragma unroll
        for (int o = 16; o; o >>= 1) { s += __shfl_xor_sync(~0u, s, o); q += __shfl_xor_sync(~0u, q, o); }
        float m = s * (1.f / 96.f);
        float rs = rsqrtf(fmaxf(q * (1.f / 96.f) - m * m, 0.f) + EPS);
        float* xao = g_pool + OF_XATT + (size_t)row * 96;
#pragma unroll
        for (int i = 0; i < 3; i++) {
            int c = lane + 32 * i;
            xao[c] = tf32f((sOut[r][c] - m) * rs * ga[c] + ba[c]);
        }
        s = 0.f; q = 0.f;
#pragma unroll
        for (int i = 0; i < 6; i++) { float v = sOut[r][96 + lane + 32 * i]; s += v; q += v * v; }
#pragma unroll
        for (int o = 16; o; o >>= 1) { s += __shfl_xor_sync(~0u, s, o); q += __shfl_xor_sync(~0u, q, o); }
        m = s * (1.f / 192.f);
        rs = rsqrtf(fmaxf(q * (1.f / 192.f) - m * m, 0.f) + EPS);
        float* va = g_pool + OF_VOLA + (size_t)spatial_of_row(row) * 192;
#pragma unroll
        for (int i = 0; i < 6; i++) {
            int c = lane + 32 * i;
            va[c] = (sOut[r][96 + c] - m) * rs * gc[c] + bc[c];
        }
    }
}

// ============================================================
// K2: depthwise conv 3x3x3 + bias, partial stats
// zero-stripe bases, rolling loop with 1-iter load lookahead
// ============================================================
__global__ __launch_bounds__(192) void k_dwconv(
    const float* __restrict__ dww, const float* __restrict__ dwb)
{
    const float* vin = g_pool + OF_VOLA;
    float* vout = g_pool + OF_VOLB;
    int c = threadIdx.x;
    int blk = blockIdx.x;
    int b = blk >> 10, z = (blk >> 5) & 31, y = blk & 31;

    float w[27];
#pragma unroll
    for (int i = 0; i < 27; i++) w[i] = dww[c * 27 + i];
    float bias = dwb[c];

    const float* base[9];
#pragma unroll
    for (int dz = 0; dz < 3; dz++)
#pragma unroll
        for (int dy = 0; dy < 3; dy++) {
            int l = dz * 3 + dy;
            int zz = z + dz - 1, yy = y + dy - 1;
            bool ok = (zz >= 0 && zz < 32 && yy >= 0 && yy < 32);
            base[l] = ok ? (vin + ((size_t)((b * 32 + zz) * 32 + yy) * 32) * 192 + c)
                         : (g_pool + OF_ZROW + c);
        }

    float p0[9], p1[9], p2[9];
#pragma unroll
    for (int l = 0; l < 9; l++) {
        p0[l] = 0.f;
        p1[l] = base[l][0];
        p2[l] = base[l][192];
    }

    float ssum = 0.f, ssq = 0.f;
    float* orow = vout + ((size_t)blk * 32) * 192 + c;
#pragma unroll 2
    for (int xx = 0; xx < 32; xx++) {
        // prefetch next-next column while computing current
        float pn[9];
        if (xx < 30) {
#pragma unroll
            for (int l = 0; l < 9; l++) pn[l] = base[l][(xx + 2) * 192];
        } else {
#pragma unroll
            for (int l = 0; l < 9; l++) pn[l] = 0.f;
        }
        float a = bias;
#pragma unroll
        for (int l = 0; l < 9; l++)
            a += w[l * 3 + 0] * p0[l] + w[l * 3 + 1] * p1[l] + w[l * 3 + 2] * p2[l];
        orow[xx * 192] = a;
        ssum += a; ssq += a * a;
#pragma unroll
        for (int l = 0; l < 9; l++) { p0[l] = p1[l]; p1[l] = p2[l]; p2[l] = pn[l]; }
    }
    g_pool[OF_PCS + (size_t)blk * 192 + c] = ssum;
    g_pool[OF_PCQ + (size_t)blk * 192 + c] = ssq;
}

// ============================================================
// reductions
// ============================================================
__global__ __launch_bounds__(128) void k_redstats(
    unsigned long long ofs, unsigned long long ofq, int nchunk, int C, float invN,
    unsigned long long ofm, unsigned long long ofr)
{
    __shared__ float ss[128], qq[128];
    int g = blockIdx.x; int b = g / C, c = g % C;
    float s = 0.f, q = 0.f;
    for (int i = threadIdx.x; i < nchunk; i += 128) {
        size_t o = ((size_t)b * nchunk + i) * C + c;
        s += g_pool[ofs + o]; q += g_pool[ofq + o];
    }
    ss[threadIdx.x] = s; qq[threadIdx.x] = q; __syncthreads();
    for (int o = 64; o; o >>= 1) {
        if (threadIdx.x < o) { ss[threadIdx.x] += ss[threadIdx.x + o]; qq[threadIdx.x] += qq[threadIdx.x + o]; }
        __syncthreads();
    }
    if (threadIdx.x == 0) {
        float m = ss[0] * invN;
        g_pool[ofm + g] = m;
        g_pool[ofr + g] = rsqrtf(fmaxf(qq[0] * invN - m * m, 0.f) + EPS);
    }
}

__global__ __launch_bounds__(128) void k_redmean(
    unsigned long long ofs, int nchunk, int C, float invN, unsigned long long ofm)
{
    __shared__ float ss[128];
    int g = blockIdx.x; int b = g / C, c = g % C;
    float s = 0.f;
    for (int i = threadIdx.x; i < nchunk; i += 128)
        s += g_pool[ofs + ((size_t)b * nchunk + i) * C + c];
    ss[threadIdx.x] = s; __syncthreads();
    for (int o = 64; o; o >>= 1) {
        if (threadIdx.x < o) ss[threadIdx.x] += ss[threadIdx.x + o];
        __syncthreads();
    }
    if (threadIdx.x == 0) g_pool[ofm + g] = ss[0] * invN;
}

// ============================================================
// K4: pooled partials only
// ============================================================
__global__ __launch_bounds__(192) void k_pool()
{
    int c = threadIdx.x;
    int blk = blockIdx.x; int b = blk >> 10;
    float m = g_pool[OF_M1 + b * 192 + c], rs = g_pool[OF_R1 + b * 192 + c];
    const float* v = g_pool + OF_VOLB + ((size_t)blk * 32) * 192 + c;
    float s = 0.f;
    for (int xx = 0; xx < 32; xx++)
        s += geluf((v[(size_t)xx * 192] - m) * rs);
    g_pool[OF_PPOOL + (size_t)blk * 192 + c] = s;
}

// ============================================================
// K5: ci MLP
// ============================================================
__global__ __launch_bounds__(96) void k_ci(
    const float* __restrict__ w1, const float* __restrict__ b1,
    const float* __restrict__ w2, const float* __restrict__ b2, int nb)
{
    __shared__ float t24[24];
    int tid = threadIdx.x;
    for (int b = 0; b < nb; b++) {
        if (tid < 24) {
            float s = b1[tid];
            for (int c = 0; c < 192; c++) s += g_pool[OF_POOLED + b * 192 + c] * w1[c * 24 + tid];
            t24[tid] = geluf(s);
        }
        __syncthreads();
        {
            float s = b2[tid];
#pragma unroll
            for (int j = 0; j < 24; j++) s += t24[j] * w2[j * 96 + tid];
            g_pool[OF_GATE + b * 96 + tid] = 1.f / (1.f + expf(-s));
        }
        __syncthreads();
    }
}

// ============================================================
// K6: pj conv1x1 (pre-tf32 W, fused inorm+gelu A)
// ============================================================
__global__ __launch_bounds__(256) void k_pj(const float* __restrict__ pb)
{
    __shared__ float sA[64][36];
    __shared__ float sW[32][104];
    const int tid = threadIdx.x, warp = tid >> 5, lane = tid & 31;
    const int g = lane >> 2, t = lane & 3;
    const int wm = warp >> 2, wn = warp & 3;
    const int row0 = blockIdx.x * 64;
    const int b = row0 >> 15;
    const int mrow = wm * 32;
    const float* vb = g_pool + OF_VOLB;
    const float* wpj = g_pool + OF_WPJ;
    const float* M1 = g_pool + OF_M1 + b * 192;
    const float* R1 = g_pool + OF_R1 + b * 192;

    float4 acc[2][3];
#pragma unroll
    for (int mt = 0; mt < 2; mt++)
#pragma unroll
        for (int j = 0; j < 3; j++) acc[mt][j] = make_float4(0.f, 0.f, 0.f, 0.f);

    for (int kb = 0; kb < 192; kb += 32) {
#pragma unroll
        for (int i = 0; i < 2; i++) {
            int idx = tid * 2 + i; int r = idx >> 3, c = (idx & 7) * 4;
            float4 v = *(const float4*)(vb + (size_t)spatial_of_row(row0 + r) * 192 + kb + c);
            int ch = kb + c;
            sA[r][c]     = tf32f(geluf((v.x - M1[ch])     * R1[ch]));
            sA[r][c + 1] = tf32f(geluf((v.y - M1[ch + 1]) * R1[ch + 1]));
            sA[r][c + 2] = tf32f(geluf((v.z - M1[ch + 2]) * R1[ch + 2]));
            sA[r][c + 3] = tf32f(geluf((v.w - M1[ch + 3]) * R1[ch + 3]));
        }
#pragma unroll
        for (int i = 0; i < 3; i++) {
            int idx = tid + i * 256; int r = idx / 24, c = (idx % 24) * 4;
            *(float4*)&sW[r][c] = *(const float4*)(wpj + (size_t)(kb + r) * 96 + c);
        }
        __syncthreads();
#pragma unroll
        for (int sk = 0; sk < 32; sk += 8) {
            unsigned a0[2], a1[2], a2[2], a3[2];
#pragma unroll
            for (int mt = 0; mt < 2; mt++) {
                int r = mrow + mt * 16;
                a0[mt] = __float_as_uint(sA[r + g][sk + t]);
                a1[mt] = __float_as_uint(sA[r + g + 8][sk + t]);
                a2[mt] = __float_as_uint(sA[r + g][sk + t + 4]);
                a3[mt] = __float_as_uint(sA[r + g + 8][sk + t + 4]);
            }
#pragma unroll
            for (int j = 0; j < 3; j++) {
                int n0 = wn * 24 + j * 8;
                unsigned b0v = __float_as_uint(sW[sk + t][n0 + g]);
                unsigned b1v = __float_as_uint(sW[sk + t + 4][n0 + g]);
                mma8(acc[0][j], a0[0], a1[0], a2[0], a3[0], b0v, b1v);
                mma8(acc[1][j], a0[1], a1[1], a2[1], a3[1], b0v, b1v);
            }
        }
        __syncthreads();
    }
    float* vp = g_pool + OF_VOLP;
#pragma unroll
    for (int mt = 0; mt < 2; mt++) {
        int r0 = row0 + mrow + mt * 16 + g, r1 = r0 + 8;
#pragma unroll
        for (int j = 0; j < 3; j++) {
            int c = wn * 24 + j * 8 + 2 * t;
            float bx = pb[c], by = pb[c + 1];
            *(float2*)&vp[(size_t)r0 * 96 + c] = make_float2(acc[mt][j].x + bx, acc[mt][j].y + by);
            *(float2*)&vp[(size_t)r1 * 96 + c] = make_float2(acc[mt][j].z + bx, acc[mt][j].w + by);
        }
    }
}

// ============================================================
// K7a: qkv GEMM, K-chunk 16 double-buffered
// ============================================================
__global__ __launch_bounds__(256) void k_qkv(const float* __restrict__ qb)
{
    extern __shared__ float sm[];
    float* sAb[2] = { sm, sm + 1280 };
    float* sWb[2] = { sm + 2560, sm + 2560 + 4736 };
    const float* A = g_pool + OF_XATT;
    const float* wq = g_pool + OF_WQKV;
    const int tid = threadIdx.x, warp = tid >> 5, lane = tid & 31;
    const int g = lane >> 2, t = lane & 3;
    const int wm = warp >> 2, wn = warp & 3;
    const int row0 = blockIdx.x * 64;
    const int mrow = wm * 32;
    const int ar = tid >> 2, ac = (tid & 3) * 4;

    float4 acc[2][9];
#pragma unroll
    for (int mt = 0; mt < 2; mt++)
#pragma unroll
        for (int j = 0; j < 9; j++) acc[mt][j] = make_float4(0.f, 0.f, 0.f, 0.f);

    {
        cpa16(sAb[0] + ar * 20 + ac, A + (size_t)(row0 + ar) * 96 + ac);
#pragma unroll
        for (int i = 0; i < 5; i++) {
            int idx = tid + i * 256;
            if (idx < 1152) {
                int r = idx / 72, c = (idx % 72) * 4;
                cpa16(sWb[0] + r * 296 + c, wq + (size_t)r * 288 + c);
            }
        }
        CP_COMMIT();
    }

    for (int it = 0; it < 6; it++) {
        int buf = it & 1;
        if (it < 5) {
            int kb = (it + 1) * 16, nb = buf ^ 1;
            cpa16(sAb[nb] + ar * 20 + ac, A + (size_t)(row0 + ar) * 96 + kb + ac);
#pragma unroll
            for (int i = 0; i < 5; i++) {
                int idx = tid + i * 256;
                if (idx < 1152) {
                    int r = idx / 72, c = (idx % 72) * 4;
                    cpa16(sWb[nb] + r * 296 + c, wq + (size_t)(kb + r) * 288 + c);
                }
            }
            CP_COMMIT();
            CP_WAIT1();
        } else {
            CP_WAIT0();
        }
        __syncthreads();
        const float* sA = sAb[buf];
        const float* sW = sWb[buf];
#pragma unroll
        for (int sk = 0; sk < 16; sk += 8) {
            unsigned a0[2], a1[2], a2[2], a3[2];
#pragma unroll
            for (int mt = 0; mt < 2; mt++) {
                int r = mrow + mt * 16;
                a0[mt] = __float_as_uint(sA[(r + g) * 20 + sk + t]);
                a1[mt] = __float_as_uint(sA[(r + g + 8) * 20 + sk + t]);
                a2[mt] = __float_as_uint(sA[(r + g) * 20 + sk + t + 4]);
                a3[mt] = __float_as_uint(sA[(r + g + 8) * 20 + sk + t + 4]);
            }
#pragma unroll
            for (int j = 0; j < 9; j++) {
                int n0 = wn * 72 + j * 8;
                unsigned b0v = __float_as_uint(sW[(sk + t) * 296 + n0 + g]);
                unsigned b1v = __float_as_uint(sW[(sk + t + 4) * 296 + n0 + g]);
                mma8(acc[0][j], a0[0], a1[0], a2[0], a3[0], b0v, b1v);
                mma8(acc[1][j], a0[1], a1[1], a2[1], a3[1], b0v, b1v);
            }
        }
        __syncthreads();
    }
    float* Q = g_pool + OF_QKV + (size_t)blockIdx.x * 18432;
    const float* gate = g_pool + OF_GATE + (blockIdx.x >> 9) * 96;
#pragma unroll
    for (int mt = 0; mt < 2; mt++) {
        int n0r = mrow + mt * 16 + g, n1r = n0r + 8;
#pragma unroll
        for (int j = 0; j < 9; j++) {
            int c = wn * 72 + j * 8 + 2 * t;
            int s = c / 96, rem = c - s * 96, h = rem >> 4, d = rem & 15;
            float bx = qb[c], by = qb[c + 1];
            float x0 = acc[mt][j].x + bx, y0 = acc[mt][j].y + by;
            float z0 = acc[mt][j].z + bx, w0 = acc[mt][j].w + by;
            if (s == 0) { x0 *= 0.25f; y0 *= 0.25f; z0 *= 0.25f; w0 *= 0.25f; }
            else if (s == 2) {
                float g0 = gate[rem], g1 = gate[rem + 1];
                x0 *= g0; y0 *= g1; z0 *= g0; w0 *= g1;
            }
            float* dst = Q + s * 6144 + h * 1024 + d;
            *(float2*)(dst + n0r * 16) = make_float2(x0, y0);
            *(float2*)(dst + n1r * 16) = make_float2(z0, w0);
        }
    }
}

// ============================================================
// K7b: attention per window (vectorized smem, pad 20)
// ============================================================
__global__ __launch_bounds__(256) void k_attn()
{
    __shared__ float qS[64][20], kS[64][20], vS[64][20];
    __shared__ float pS[64][65];
    int tid = threadIdx.x;
    int win = blockIdx.x;
    const float* qkv = g_pool + OF_QKV + (size_t)win * 18432;
    const float* biasT = g_pool + OF_BIAS;
    float* out = g_pool + OF_AOUT + (size_t)win * 64 * 96;
    int warp = tid >> 5, lane = tid & 31;
    int sn = tid >> 2, sd = (tid & 3) * 4;

    for (int hh = 0; hh < 6; hh++) {
        {
            const float* base = qkv + hh * 1024 + sn * 16 + sd;
            *(float4*)&qS[sn][sd] = *(const float4*)(base);
            *(float4*)&kS[sn][sd] = *(const float4*)(base + 6144);
            *(float4*)&vS[sn][sd] = *(const float4*)(base + 12288);
        }
        __syncthreads();
        for (int rr = 0; rr < 8; rr++) {
            int n = warp * 8 + rr;
            int m0 = lane, m1 = lane + 32;
            float s0 = biasT[hh * 4096 + n * 64 + m0];
            float s1 = biasT[hh * 4096 + n * 64 + m1];
#pragma unroll
            for (int d4 = 0; d4 < 4; d4++) {
                float4 qv = *(const float4*)&qS[n][d4 * 4];
                float4 k0 = *(const float4*)&kS[m0][d4 * 4];
                float4 k1 = *(const float4*)&kS[m1][d4 * 4];
                s0 += qv.x * k0.x + qv.y * k0.y + qv.z * k0.z + qv.w * k0.w;
                s1 += qv.x * k1.x + qv.y * k1.y + qv.z * k1.z + qv.w * k1.w;
            }
            float mx = fmaxf(s0, s1);
#pragma unroll
            for (int o = 16; o; o >>= 1) mx = fmaxf(mx, __shfl_xor_sync(~0u, mx, o));
            float e0 = expf(s0 - mx), e1 = expf(s1 - mx);
            float sum = e0 + e1;
#pragma unroll
            for (int o = 16; o; o >>= 1) sum += __shfl_xor_sync(~0u, sum, o);
            float inv = 1.f / sum;
            pS[n][m0] = e0 * inv;
            pS[n][m1] = e1 * inv;
        }
        __syncthreads();
        {
            int n = tid >> 2, dg = tid & 3;
            float a0 = 0.f, a1 = 0.f, a2 = 0.f, a3 = 0.f;
#pragma unroll
            for (int m = 0; m < 64; m++) {
                float pm = pS[n][m];
                float4 v = *(const float4*)&vS[m][dg * 4];
                a0 += pm * v.x; a1 += pm * v.y; a2 += pm * v.z; a3 += pm * v.w;
            }
            size_t ob = (size_t)n * 96 + hh * 16 + dg * 4;
            *(float4*)(out + ob) = make_float4(a0, a1, a2, a3);
        }
        __syncthreads();
    }
}

// ============================================================
// K8a: si stage 1
// ============================================================
__global__ __launch_bounds__(256) void k_si1(
    const float* __restrict__ w1, const float* __restrict__ b1)
{
    __shared__ float aS[64][97];
    __shared__ float wS[96 * 12];
    __shared__ float sb[64][12];
    int tid = threadIdx.x;
    int blk = blockIdx.x; int row0 = blk * 64;
    const float* A = g_pool + OF_AOUT;
    for (int i = tid; i < 96 * 12; i += 256) wS[i] = w1[i];
    for (int i = tid; i < 64 * 96; i += 256) {
        int r = i / 96, c = i % 96;
        aS[r][c] = A[(size_t)(row0 + r) * 96 + c];
    }
    __syncthreads();
    {
        int r = tid >> 2, jg = tid & 3;
        float s0 = b1[jg * 3 + 0], s1 = b1[jg * 3 + 1], s2 = b1[jg * 3 + 2];
        for (int c = 0; c < 96; c++) {
            float a = aS[r][c];
            s0 += a * wS[c * 12 + jg * 3 + 0];
            s1 += a * wS[c * 12 + jg * 3 + 1];
            s2 += a * wS[c * 12 + jg * 3 + 2];
        }
        float* o = g_pool + OF_S12 + (size_t)(row0 + r) * 12 + jg * 3;
        o[0] = s0; o[1] = s1; o[2] = s2;
        sb[r][jg * 3 + 0] = s0; sb[r][jg * 3 + 1] = s1; sb[r][jg * 3 + 2] = s2;
    }
    __syncthreads();
    if (tid < 12) {
        float S = 0.f, Q = 0.f;
        for (int r = 0; r < 64; r++) { float v = sb[r][tid]; S += v; Q += v * v; }
        g_pool[OF_P12S + (size_t)blk * 12 + tid] = S;
        g_pool[OF_P12Q + (size_t)blk * 12 + tid] = Q;
    }
}

// ============================================================
// K8c: gate + multiply + partials
// ============================================================
__global__ __launch_bounds__(96) void k_gatemul(
    const float* __restrict__ w2, const float* __restrict__ b2)
{
    __shared__ float gb[64];
    int tid = threadIdx.x;
    int blk = blockIdx.x; int row0 = blk * 64; int b = row0 >> 15;
    if (tid < 64) {
        const float* s = g_pool + OF_S12 + (size_t)(row0 + tid) * 12;
        float a = b2[0];
#pragma unroll
        for (int j = 0; j < 12; j++) {
            float v = (s[j] - g_pool[OF_M2 + b * 12 + j]) * g_pool[OF_R2 + b * 12 + j];
            a += geluf(v) * w2[j];
        }
        gb[tid] = 1.f / (1.f + expf(-a));
    }
    __syncthreads();
    const float* vp = g_pool + OF_VOLP + (size_t)row0 * 96 + tid;
    float* yv = g_pool + OF_YV + (size_t)row0 * 96 + tid;
    float ss = 0.f, sq = 0.f;
    for (int r = 0; r < 64; r++) {
        float y = gb[r] * vp[(size_t)r * 96];
        yv[(size_t)r * 96] = y;
        ss += y; sq += y * y;
    }
    g_pool[OF_PYS + (size_t)blk * 96 + tid] = ss;
    g_pool[OF_PYQ + (size_t)blk * 96 + tid] = sq;
}

// ============================================================
// K9: final (tf32 mma, K-chunk 16 double-buffered W, 3 CTA/SM)
// ============================================================
__global__ __launch_bounds__(256, 3) void k_final(
    const float* __restrict__ bp,
    const float* __restrict__ ga, const float* __restrict__ ba,
    float* __restrict__ out)
{
    extern __shared__ float sm[];
    float (*sA)[196] = (float(*)[196])sm;
    float* sWb[2] = { sm + 12544, sm + 12544 + 3200 };
    const float* wp = g_pool + OF_WPROJ;
    const int tid = threadIdx.x, warp = tid >> 5, lane = tid & 31;
    const int g = lane >> 2, t = lane & 3;
    const int wm = warp >> 2, wn = warp & 3;
    const int row0 = blockIdx.x * 64; const int b = row0 >> 15;
    const int mrow = wm * 32;
    const float* A = g_pool + OF_AOUT;
    const float* Y = g_pool + OF_YV;

    {
#pragma unroll
        for (int i = 0; i < 3; i++) {
            int idx = tid + i * 256; int r = idx / 48, c = (idx % 48) * 4;
            cpa16(sWb[0] + r * 200 + c, wp + (size_t)r * 192 + c);
        }
        CP_COMMIT();
    }

    for (int it = 0; it < 8; it++) {
        int r = warp * 8 + it;
        int row = row0 + r;
        float s = 0.f, q = 0.f;
        float vals[3];
#pragma unroll
        for (int i = 0; i < 3; i++) {
            vals[i] = A[(size_t)row * 96 + lane + 32 * i];
            s += vals[i]; q += vals[i] * vals[i];
        }
#pragma unroll
        for (int o = 16; o; o >>= 1) { s += __shfl_xor_sync(~0u, s, o); q += __shfl_xor_sync(~0u, q, o); }
        float m = s * (1.f / 96.f);
        float rs = rsqrtf(fmaxf(q * (1.f / 96.f) - m * m, 0.f) + EPS);
#pragma unroll
        for (int i = 0; i < 3; i++) {
            int c = lane + 32 * i;
            sA[r][c] = tf32f((vals[i] - m) * rs * ga[c] + ba[c]);
        }
#pragma unroll
        for (int i = 0; i < 3; i++) {
            int c = lane + 32 * i;
            float v = (Y[(size_t)row * 96 + c] - g_pool[OF_M3 + b * 96 + c]) * g_pool[OF_R3 + b * 96 + c];
            sA[r][96 + c] = tf32f(v);
        }
    }
    __syncthreads();

    float4 acc[2][6];
#pragma unroll
    for (int mt = 0; mt < 2; mt++)
#pragma unroll
        for (int j = 0; j < 6; j++) acc[mt][j] = make_float4(0.f, 0.f, 0.f, 0.f);

    for (int it = 0; it < 12; it++) {
        int buf = it & 1;
        int kb = it * 16;
        if (it < 11) {
            int nkb = kb + 16, nb = buf ^ 1;
#pragma unroll
            for (int i = 0; i < 3; i++) {
                int idx = tid + i * 256; int r = idx / 48, c = (idx % 48) * 4;
                cpa16(sWb[nb] + r * 200 + c, wp + (size_t)(nkb + r) * 192 + c);
            }
            CP_COMMIT();
            CP_WAIT1();
        } else {
            CP_WAIT0();
        }
        __syncthreads();
        const float* sW = sWb[buf];
#pragma unroll
        for (int sk = 0; sk < 16; sk += 8) {
            unsigned a0[2], a1[2], a2[2], a3[2];
#pragma unroll
            for (int mt = 0; mt < 2; mt++) {
                int r = mrow + mt * 16;
                a0[mt] = __float_as_uint(sA[r + g][kb + sk + t]);
                a1[mt] = __float_as_uint(sA[r + g + 8][kb + sk + t]);
                a2[mt] = __float_as_uint(sA[r + g][kb + sk + t + 4]);
                a3[mt] = __float_as_uint(sA[r + g + 8][kb + sk + t + 4]);
            }
#pragma unroll
            for (int j = 0; j < 6; j++) {
                int n0 = wn * 48 + j * 8;
                unsigned b0v = __float_as_uint(sW[(sk + t) * 200 + n0 + g]);
                unsigned b1v = __float_as_uint(sW[(sk + t + 4) * 200 + n0 + g]);
                mma8(acc[0][j], a0[0], a1[0], a2[0], a3[0], b0v, b1v);
                mma8(acc[1][j], a0[1], a1[1], a2[1], a3[1], b0v, b1v);
            }
        }
        __syncthreads();
    }
#pragma unroll
    for (int mt = 0; mt < 2; mt++) {
        int r0 = row0 + mrow + mt * 16 + g, r1 = r0 + 8;
#pragma unroll
        for (int j = 0; j < 6; j++) {
            int c = wn * 48 + j * 8 + 2 * t;
            float bx = bp[c], by = bp[c + 1];
            *(float2*)&out[(size_t)r0 * 192 + c] = make_float2(acc[mt][j].x + bx, acc[mt][j].y + by);
            *(float2*)&out[(size_t)r1 * 192 + c] = make_float2(acc[mt][j].z + bx, acc[mt][j].w + by);
        }
    }
}

// ============================================================
// host launcher
// ============================================================
extern "C" void kernel_launch(void* const* d_in, const int* in_sizes, int n_in,
                              void* d_out, int out_size)
{
    const float* x       = (const float*)d_in[0];
    const float* w_pattn = (const float*)d_in[1];
    const float* b_pattn = (const float*)d_in[2];
    const float* g_aln   = (const float*)d_in[3];
    const float* b_aln   = (const float*)d_in[4];
    const float* w_pcnn  = (const float*)d_in[5];
    const float* b_pcnn  = (const float*)d_in[6];
    const float* g_cln   = (const float*)d_in[7];
    const float* b_cln   = (const float*)d_in[8];
    const float* dw_w    = (const float*)d_in[9];
    const float* dw_b    = (const float*)d_in[10];
    const float* ci_w1   = (const float*)d_in[11];
    const float* ci_b1   = (const float*)d_in[12];
    const float* ci_w2   = (const float*)d_in[13];
    const float* ci_b2   = (const float*)d_in[14];
    const float* pj_w    = (const float*)d_in[15];
    const float* pj_b    = (const float*)d_in[16];
    const float* qkv_w   = (const float*)d_in[17];
    const float* qkv_b   = (const float*)d_in[18];
    const float* si_w1   = (const float*)d_in[19];
    const float* si_b1   = (const float*)d_in[20];
    const float* si_w2   = (const float*)d_in[21];
    const float* si_b2   = (const float*)d_in[22];
    const float* g_anorm = (const float*)d_in[23];
    const float* b_anorm = (const float*)d_in[24];
    const float* w_proj  = (const float*)d_in[25];
    const float* b_proj  = (const float*)d_in[26];
    const float* rpb     = (const float*)d_in[27];

    const int Bwin = in_sizes[0] / (64 * 192);   // 2048
    const int rows = Bwin * 64;                  // 131072
    const int nb   = Bwin / 512;                 // 4

    cudaFuncSetAttribute(k_embed, cudaFuncAttributeMaxDynamicSharedMemorySize, 75776);
    cudaFuncSetAttribute(k_qkv,   cudaFuncAttributeMaxDynamicSharedMemorySize, 50176);
    cudaFuncSetAttribute(k_final, cudaFuncAttributeMaxDynamicSharedMemorySize, 77824);

    // k_dwconv at launch index 3 (ncu capture slot)
    k_wprep<<<216, 256>>>(w_pattn, w_pcnn, qkv_w, w_proj, pj_w);
    k_bias<<<6, 256>>>(rpb);
    k_embed<<<rows / 64, 256, 73728>>>(x, b_pattn, g_aln, b_aln,
                                       b_pcnn, g_cln, b_cln);
    k_dwconv<<<nb * 1024, 192>>>(dw_w, dw_b);
    k_redstats<<<nb * 192, 128>>>(OF_PCS, OF_PCQ, 1024, 192, 1.f / 32768.f, OF_M1, OF_R1);
    k_pool<<<nb * 1024, 192>>>();
    k_redmean<<<nb * 192, 128>>>(OF_PPOOL, 1024, 192, 1.f / 32768.f, OF_POOLED);
    k_ci<<<1, 96>>>(ci_w1, ci_b1, ci_w2, ci_b2, nb);
    k_pj<<<rows / 64, 256>>>(pj_b);
    k_qkv<<<rows / 64, 256, 48128>>>(qkv_b);
    k_attn<<<Bwin, 256>>>();
    k_si1<<<rows / 64, 256>>>(si_w1, si_b1);
    k_redstats<<<nb * 12, 128>>>(OF_P12S, OF_P12Q, 512, 12, 1.f / 32768.f, OF_M2, OF_R2);
    k_gatemul<<<rows / 64, 96>>>(si_w2, si_b2);
    k_redstats<<<nb * 96, 128>>>(OF_PYS, OF_PYQ, 512, 96, 1.f / 32768.f, OF_M3, OF_R3);
    k_final<<<rows / 64, 256, 75776>>>(b_proj, g_anorm, b_anorm, (float*)d_out);
}

// round 16
// speedup vs baseline: 1.0476x; 1.0113x over previous
#include <cuda_runtime.h>
#include <math.h>

#define EPS 1e-5f

// ---------------- scratch pool (floats) ----------------
#define OF_VOLA   0ull
#define OF_VOLB   25165824ull
#define OF_QKV    50331648ull
#define OF_XATT   88080384ull
#define OF_AOUT   100663296ull
#define OF_VOLP   113246208ull
#define OF_YV     125829120ull
#define OF_S12    138412032ull
#define OF_PCS    139984896ull
#define OF_PCQ    140771328ull
#define OF_PPOOL  141557760ull
#define OF_P12S   142344192ull
#define OF_P12Q   142368768ull
#define OF_PYS    142393344ull
#define OF_PYQ    142589952ull
#define OF_M1     142786560ull
#define OF_R1     142787328ull
#define OF_POOLED 142788096ull
#define OF_M2     142788864ull
#define OF_R2     142788912ull
#define OF_M3     142788960ull
#define OF_R3     142789344ull
#define OF_GATE   142789728ull
#define OF_BIAS   142790144ull   // 24576
#define OF_WEMB   142814720ull   // 192*288 = 55296
#define OF_WQKV   142870016ull   // 96*288  = 27648
#define OF_WPROJ  142897664ull   // 192*192 = 36864
#define OF_WPJ    142934528ull   // 192*96  = 18432
#define OF_ZROW   142952960ull   // 6144 zeros (32*192)

__device__ float g_pool[143000000];

__device__ __forceinline__ float geluf(float x) {
    return 0.5f * x * (1.0f + erff(x * 0.70710678118654752f));
}

__device__ __forceinline__ float tf32f(float x) {
    unsigned u;
    asm("cvt.rna.tf32.f32 %0, %1;" : "=r"(u) : "f"(x));
    return __uint_as_float(u);
}

__device__ __forceinline__ void cpa16(float* dst, const float* src) {
    unsigned d = (unsigned)__cvta_generic_to_shared(dst);
    asm volatile("cp.async.ca.shared.global [%0], [%1], 16;" :: "r"(d), "l"(src));
}
#define CP_COMMIT() asm volatile("cp.async.commit_group;")
#define CP_WAIT1()  asm volatile("cp.async.wait_group 1;")
#define CP_WAIT0()  asm volatile("cp.async.wait_group 0;")

__device__ __forceinline__ void mma8(float4& d, unsigned a0, unsigned a1,
                                     unsigned a2, unsigned a3,
                                     unsigned b0, unsigned b1) {
    asm volatile(
        "mma.sync.aligned.m16n8k8.row.col.f32.tf32.tf32.f32 "
        "{%0,%1,%2,%3},{%4,%5,%6,%7},{%8,%9},{%0,%1,%2,%3};"
        : "+f"(d.x), "+f"(d.y), "+f"(d.z), "+f"(d.w)
        : "r"(a0), "r"(a1), "r"(a2), "r"(a3), "r"(b0), "r"(b1));
}

__device__ __forceinline__ int spatial_of_row(int row) {
    int win = row >> 6, n = row & 63;
    int b = win >> 9, d = (win >> 6) & 7, h = (win >> 3) & 7, w = win & 7;
    int wd = n >> 4, wh = (n >> 2) & 3, ww = n & 3;
    int Z = d * 4 + wd, Y = h * 4 + wh, X = w * 4 + ww;
    return ((b * 32 + Z) * 32 + Y) * 32 + X;
}

// ============================================================
// K-1: one-off weight prep: tf32-round all GEMM weights + zero stripe
// ============================================================
__global__ __launch_bounds__(256) void k_wprep(
    const float* __restrict__ w1, const float* __restrict__ w2,
    const float* __restrict__ qw, const float* __restrict__ pw,
    const float* __restrict__ jw)
{
    int i = blockIdx.x * 256 + threadIdx.x;
    if (i < 55296) {
        int k = i / 288, c = i % 288;
        float v = (c < 96) ? w1[k * 96 + c] : w2[k * 192 + (c - 96)];
        g_pool[OF_WEMB + i] = tf32f(v);
    }
    if (i < 27648) g_pool[OF_WQKV + i] = tf32f(qw[i]);
    if (i < 36864) g_pool[OF_WPROJ + i] = tf32f(pw[i]);
    if (i < 18432) g_pool[OF_WPJ + i] = tf32f(jw[i]);
    if (i < 6144)  g_pool[OF_ZROW + i] = 0.f;
}

// ============================================================
// K0: precompute rel-pos bias table
// ============================================================
__global__ __launch_bounds__(256) void k_bias(const float* __restrict__ rpb)
{
    int hh = blockIdx.x;
    for (int p = threadIdx.x; p < 4096; p += 256) {
        int n = p >> 6, m = p & 63;
        int nd = n >> 4, nh = (n >> 2) & 3, nw = n & 3;
        int md = m >> 4, mh = (m >> 2) & 3, mw = m & 3;
        int idx = ((nd - md + 3) * 49 + (nh - mh + 3) * 7 + (nw - mw + 3)) * 6 + hh;
        g_pool[OF_BIAS + hh * 4096 + p] = rpb[idx];
    }
}

// ============================================================
// K1: embed GEMM, K-chunk 16 double-buffered
// ============================================================
__global__ __launch_bounds__(256) void k_embed(
    const float* __restrict__ x, const float* __restrict__ b1,
    const float* __restrict__ ga, const float* __restrict__ ba,
    const float* __restrict__ b2,
    const float* __restrict__ gc, const float* __restrict__ bc)
{
    extern __shared__ float sm[];
    float* sAb[2] = { sm, sm + 1280 };
    float* sWb[2] = { sm + 2560, sm + 2560 + 4736 };
    float (*sOut)[288] = (float(*)[288])sm;
    const float* wemb = g_pool + OF_WEMB;
    const int tid = threadIdx.x, warp = tid >> 5, lane = tid & 31;
    const int g = lane >> 2, t = lane & 3;
    const int wm = warp >> 2, wn = warp & 3;
    const int row0 = blockIdx.x * 64;
    const int mrow = wm * 32;
    const int ar = tid >> 2, ac = (tid & 3) * 4;

    float4 acc[2][9];
#pragma unroll
    for (int mt = 0; mt < 2; mt++)
#pragma unroll
        for (int j = 0; j < 9; j++) acc[mt][j] = make_float4(0.f, 0.f, 0.f, 0.f);

    {
        cpa16(sAb[0] + ar * 20 + ac, x + (size_t)(row0 + ar) * 192 + ac);
#pragma unroll
        for (int i = 0; i < 5; i++) {
            int idx = tid + i * 256;
            if (idx < 1152) {
                int r = idx / 72, c = (idx % 72) * 4;
                cpa16(sWb[0] + r * 296 + c, wemb + (size_t)r * 288 + c);
            }
        }
        CP_COMMIT();
    }

    for (int it = 0; it < 12; it++) {
        int buf = it & 1;
        if (it < 11) {
            int kb = (it + 1) * 16, nb = buf ^ 1;
            cpa16(sAb[nb] + ar * 20 + ac, x + (size_t)(row0 + ar) * 192 + kb + ac);
#pragma unroll
            for (int i = 0; i < 5; i++) {
                int idx = tid + i * 256;
                if (idx < 1152) {
                    int r = idx / 72, c = (idx % 72) * 4;
                    cpa16(sWb[nb] + r * 296 + c, wemb + (size_t)(kb + r) * 288 + c);
                }
            }
            CP_COMMIT();
            CP_WAIT1();
        } else {
            CP_WAIT0();
        }
        __syncthreads();
        const float* sA = sAb[buf];
        const float* sW = sWb[buf];
#pragma unroll
        for (int sk = 0; sk < 16; sk += 8) {
            unsigned a0[2], a1[2], a2[2], a3[2];
#pragma unroll
            for (int mt = 0; mt < 2; mt++) {
                int r = mrow + mt * 16;
                a0[mt] = __float_as_uint(tf32f(sA[(r + g) * 20 + sk + t]));
                a1[mt] = __float_as_uint(tf32f(sA[(r + g + 8) * 20 + sk + t]));
                a2[mt] = __float_as_uint(tf32f(sA[(r + g) * 20 + sk + t + 4]));
                a3[mt] = __float_as_uint(tf32f(sA[(r + g + 8) * 20 + sk + t + 4]));
            }
#pragma unroll
            for (int j = 0; j < 9; j++) {
                int n0 = wn * 72 + j * 8;
                unsigned b0v = __float_as_uint(sW[(sk + t) * 296 + n0 + g]);
                unsigned b1v = __float_as_uint(sW[(sk + t + 4) * 296 + n0 + g]);
                mma8(acc[0][j], a0[0], a1[0], a2[0], a3[0], b0v, b1v);
                mma8(acc[1][j], a0[1], a1[1], a2[1], a3[1], b0v, b1v);
            }
        }
        __syncthreads();
    }
#pragma unroll
    for (int mt = 0; mt < 2; mt++) {
        int r0 = mrow + mt * 16 + g, r1 = r0 + 8;
#pragma unroll
        for (int j = 0; j < 9; j++) {
            int c = wn * 72 + j * 8 + 2 * t;
            float bx = (c < 96) ? b1[c] : b2[c - 96];
            float by = (c + 1 < 96) ? b1[c + 1] : b2[c + 1 - 96];
            sOut[r0][c] = acc[mt][j].x + bx; sOut[r0][c + 1] = acc[mt][j].y + by;
            sOut[r1][c] = acc[mt][j].z + bx; sOut[r1][c + 1] = acc[mt][j].w + by;
        }
    }
    __syncthreads();

    for (int r = warp; r < 64; r += 8) {
        int row = row0 + r;
        float s = 0.f, q = 0.f;
#pragma unroll
        for (int i = 0; i < 3; i++) { float v = sOut[r][lane + 32 * i]; s += v; q += v * v; }
#pragma unroll
        for (int o = 16; o; o >>= 1) { s += __shfl_xor_sync(~0u, s, o); q += __shfl_xor_sync(~0u, q, o); }
        float m = s * (1.f / 96.f);
        float rs = rsqrtf(fmaxf(q * (1.f / 96.f) - m * m, 0.f) + EPS);
        float* xao = g_pool + OF_XATT + (size_t)row * 96;
#pragma unroll
        for (int i = 0; i < 3; i++) {
            int c = lane + 32 * i;
            xao[c] = tf32f((sOut[r][c] - m) * rs * ga[c] + ba[c]);
        }
        s = 0.f; q = 0.f;
#pragma unroll
        for (int i = 0; i < 6; i++) { float v = sOut[r][96 + lane + 32 * i]; s += v; q += v * v; }
#pragma unroll
        for (int o = 16; o; o >>= 1) { s += __shfl_xor_sync(~0u, s, o); q += __shfl_xor_sync(~0u, q, o); }
        m = s * (1.f / 192.f);
        rs = rsqrtf(fmaxf(q * (1.f / 192.f) - m * m, 0.f) + EPS);
        float* va = g_pool + OF_VOLA + (size_t)spatial_of_row(row) * 192;
#pragma unroll
        for (int i = 0; i < 6; i++) {
            int c = lane + 32 * i;
            va[c] = (sOut[r][96 + c] - m) * rs * gc[c] + bc[c];
        }
    }
}

// ============================================================
// K2: depthwise conv 3x3x3 + bias, partial stats
// zero-stripe bases, scatter-accumulate rolling outputs
// ============================================================
__global__ __launch_bounds__(192, 4) void k_dwconv(
    const float* __restrict__ dww, const float* __restrict__ dwb)
{
    const float* vin = g_pool + OF_VOLA;
    float* vout = g_pool + OF_VOLB;
    int c = threadIdx.x;
    int blk = blockIdx.x;
    int b = blk >> 10, z = (blk >> 5) & 31, y = blk & 31;

    float w[27];
#pragma unroll
    for (int i = 0; i < 27; i++) w[i] = dww[c * 27 + i];
    float bias = dwb[c];

    const float* base[9];
#pragma unroll
    for (int dz = 0; dz < 3; dz++)
#pragma unroll
        for (int dy = 0; dy < 3; dy++) {
            int l = dz * 3 + dy;
            int zz = z + dz - 1, yy = y + dy - 1;
            bool ok = (zz >= 0 && zz < 32 && yy >= 0 && yy < 32);
            base[l] = ok ? (vin + ((size_t)((b * 32 + zz) * 32 + yy) * 32) * 192 + c)
                         : (g_pool + OF_ZROW + c);
        }

    float colA[9], colB[9];
#pragma unroll
    for (int l = 0; l < 9; l++) colA[l] = base[l][0];

    float accA = 0.f, accB = bias, accC;
    float ssum = 0.f, ssq = 0.f;
    float* orow = vout + ((size_t)blk * 32) * 192 + c;

#pragma unroll 2
    for (int cx = 0; cx < 32; cx++) {
        float* cur = (cx & 1) ? colB : colA;
        float* nxt = (cx & 1) ? colA : colB;
        if (cx < 31) {
#pragma unroll
            for (int l = 0; l < 9; l++) nxt[l] = base[l][(cx + 1) * 192];
        }
        float a2 = 0.f, a1 = 0.f, a0 = 0.f;
#pragma unroll
        for (int l = 0; l < 9; l++) {
            a2 += w[l * 3 + 2] * cur[l];
            a1 += w[l * 3 + 1] * cur[l];
            a0 += w[l * 3 + 0] * cur[l];
        }
        accA += a2;
        accB += a1;
        accC = bias + a0;
        if (cx >= 1) {
            orow[(cx - 1) * 192] = accA;
            ssum += accA; ssq += accA * accA;
        }
        accA = accB; accB = accC;
    }
    // out[31]: missing w2*col[32] which is zero
    orow[31 * 192] = accA;
    ssum += accA; ssq += accA * accA;

    g_pool[OF_PCS + (size_t)blk * 192 + c] = ssum;
    g_pool[OF_PCQ + (size_t)blk * 192 + c] = ssq;
}

// ============================================================
// reductions
// ============================================================
__global__ __launch_bounds__(128) void k_redstats(
    unsigned long long ofs, unsigned long long ofq, int nchunk, int C, float invN,
    unsigned long long ofm, unsigned long long ofr)
{
    __shared__ float ss[128], qq[128];
    int g = blockIdx.x; int b = g / C, c = g % C;
    float s = 0.f, q = 0.f;
    for (int i = threadIdx.x; i < nchunk; i += 128) {
        size_t o = ((size_t)b * nchunk + i) * C + c;
        s += g_pool[ofs + o]; q += g_pool[ofq + o];
    }
    ss[threadIdx.x] = s; qq[threadIdx.x] = q; __syncthreads();
    for (int o = 64; o; o >>= 1) {
        if (threadIdx.x < o) { ss[threadIdx.x] += ss[threadIdx.x + o]; qq[threadIdx.x] += qq[threadIdx.x + o]; }
        __syncthreads();
    }
    if (threadIdx.x == 0) {
        float m = ss[0] * invN;
        g_pool[ofm + g] = m;
        g_pool[ofr + g] = rsqrtf(fmaxf(qq[0] * invN - m * m, 0.f) + EPS);
    }
}

__global__ __launch_bounds__(128) void k_redmean(
    unsigned long long ofs, int nchunk, int C, float invN, unsigned long long ofm)
{
    __shared__ float ss[128];
    int g = blockIdx.x; int b = g / C, c = g % C;
    float s = 0.f;
    for (int i = threadIdx.x; i < nchunk; i += 128)
        s += g_pool[ofs + ((size_t)b * nchunk + i) * C + c];
    ss[threadIdx.x] = s; __syncthreads();
    for (int o = 64; o; o >>= 1) {
        if (threadIdx.x < o) ss[threadIdx.x] += ss[threadIdx.x + o];
        __syncthreads();
    }
    if (threadIdx.x == 0) g_pool[ofm + g] = ss[0] * invN;
}

// ============================================================
// K4: pooled partials only
// ============================================================
__global__ __launch_bounds__(192) void k_pool()
{
    int c = threadIdx.x;
    int blk = blockIdx.x; int b = blk >> 10;
    float m = g_pool[OF_M1 + b * 192 + c], rs = g_pool[OF_R1 + b * 192 + c];
    const float* v = g_pool + OF_VOLB + ((size_t)blk * 32) * 192 + c;
    float s = 0.f;
    for (int xx = 0; xx < 32; xx++)
        s += geluf((v[(size_t)xx * 192] - m) * rs);
    g_pool[OF_PPOOL + (size_t)blk * 192 + c] = s;
}

// ============================================================
// K5: ci MLP
// ============================================================
__global__ __launch_bounds__(96) void k_ci(
    const float* __restrict__ w1, const float* __restrict__ b1,
    const float* __restrict__ w2, const float* __restrict__ b2, int nb)
{
    __shared__ float t24[24];
    int tid = threadIdx.x;
    for (int b = 0; b < nb; b++) {
        if (tid < 24) {
            float s = b1[tid];
            for (int c = 0; c < 192; c++) s += g_pool[OF_POOLED + b * 192 + c] * w1[c * 24 + tid];
            t24[tid] = geluf(s);
        }
        __syncthreads();
        {
            float s = b2[tid];
#pragma unroll
            for (int j = 0; j < 24; j++) s += t24[j] * w2[j * 96 + tid];
            g_pool[OF_GATE + b * 96 + tid] = 1.f / (1.f + expf(-s));
        }
        __syncthreads();
    }
}

// ============================================================
// K6: pj conv1x1 (pre-tf32 W, fused inorm+gelu A)
// ============================================================
__global__ __launch_bounds__(256) void k_pj(const float* __restrict__ pb)
{
    __shared__ float sA[64][36];
    __shared__ float sW[32][104];
    const int tid = threadIdx.x, warp = tid >> 5, lane = tid & 31;
    const int g = lane >> 2, t = lane & 3;
    const int wm = warp >> 2, wn = warp & 3;
    const int row0 = blockIdx.x * 64;
    const int b = row0 >> 15;
    const int mrow = wm * 32;
    const float* vb = g_pool + OF_VOLB;
    const float* wpj = g_pool + OF_WPJ;
    const float* M1 = g_pool + OF_M1 + b * 192;
    const float* R1 = g_pool + OF_R1 + b * 192;

    float4 acc[2][3];
#pragma unroll
    for (int mt = 0; mt < 2; mt++)
#pragma unroll
        for (int j = 0; j < 3; j++) acc[mt][j] = make_float4(0.f, 0.f, 0.f, 0.f);

    for (int kb = 0; kb < 192; kb += 32) {
#pragma unroll
        for (int i = 0; i < 2; i++) {
            int idx = tid * 2 + i; int r = idx >> 3, c = (idx & 7) * 4;
            float4 v = *(const float4*)(vb + (size_t)spatial_of_row(row0 + r) * 192 + kb + c);
            int ch = kb + c;
            sA[r][c]     = tf32f(geluf((v.x - M1[ch])     * R1[ch]));
            sA[r][c + 1] = tf32f(geluf((v.y - M1[ch + 1]) * R1[ch + 1]));
            sA[r][c + 2] = tf32f(geluf((v.z - M1[ch + 2]) * R1[ch + 2]));
            sA[r][c + 3] = tf32f(geluf((v.w - M1[ch + 3]) * R1[ch + 3]));
        }
#pragma unroll
        for (int i = 0; i < 3; i++) {
            int idx = tid + i * 256; int r = idx / 24, c = (idx % 24) * 4;
            *(float4*)&sW[r][c] = *(const float4*)(wpj + (size_t)(kb + r) * 96 + c);
        }
        __syncthreads();
#pragma unroll
        for (int sk = 0; sk < 32; sk += 8) {
            unsigned a0[2], a1[2], a2[2], a3[2];
#pragma unroll
            for (int mt = 0; mt < 2; mt++) {
                int r = mrow + mt * 16;
                a0[mt] = __float_as_uint(sA[r + g][sk + t]);
                a1[mt] = __float_as_uint(sA[r + g + 8][sk + t]);
                a2[mt] = __float_as_uint(sA[r + g][sk + t + 4]);
                a3[mt] = __float_as_uint(sA[r + g + 8][sk + t + 4]);
            }
#pragma unroll
            for (int j = 0; j < 3; j++) {
                int n0 = wn * 24 + j * 8;
                unsigned b0v = __float_as_uint(sW[sk + t][n0 + g]);
                unsigned b1v = __float_as_uint(sW[sk + t + 4][n0 + g]);
                mma8(acc[0][j], a0[0], a1[0], a2[0], a3[0], b0v, b1v);
                mma8(acc[1][j], a0[1], a1[1], a2[1], a3[1], b0v, b1v);
            }
        }
        __syncthreads();
    }
    float* vp = g_pool + OF_VOLP;
#pragma unroll
    for (int mt = 0; mt < 2; mt++) {
        int r0 = row0 + mrow + mt * 16 + g, r1 = r0 + 8;
#pragma unroll
        for (int j = 0; j < 3; j++) {
            int c = wn * 24 + j * 8 + 2 * t;
            float bx = pb[c], by = pb[c + 1];
            *(float2*)&vp[(size_t)r0 * 96 + c] = make_float2(acc[mt][j].x + bx, acc[mt][j].y + by);
            *(float2*)&vp[(size_t)r1 * 96 + c] = make_float2(acc[mt][j].z + bx, acc[mt][j].w + by);
        }
    }
}

// ============================================================
// K7a: qkv GEMM, K-chunk 16 double-buffered
// ============================================================
__global__ __launch_bounds__(256) void k_qkv(const float* __restrict__ qb)
{
    extern __shared__ float sm[];
    float* sAb[2] = { sm, sm + 1280 };
    float* sWb[2] = { sm + 2560, sm + 2560 + 4736 };
    const float* A = g_pool + OF_XATT;
    const float* wq = g_pool + OF_WQKV;
    const int tid = threadIdx.x, warp = tid >> 5, lane = tid & 31;
    const int g = lane >> 2, t = lane & 3;
    const int wm = warp >> 2, wn = warp & 3;
    const int row0 = blockIdx.x * 64;
    const int mrow = wm * 32;
    const int ar = tid >> 2, ac = (tid & 3) * 4;

    float4 acc[2][9];
#pragma unroll
    for (int mt = 0; mt < 2; mt++)
#pragma unroll
        for (int j = 0; j < 9; j++) acc[mt][j] = make_float4(0.f, 0.f, 0.f, 0.f);

    {
        cpa16(sAb[0] + ar * 20 + ac, A + (size_t)(row0 + ar) * 96 + ac);
#pragma unroll
        for (int i = 0; i < 5; i++) {
            int idx = tid + i * 256;
            if (idx < 1152) {
                int r = idx / 72, c = (idx % 72) * 4;
                cpa16(sWb[0] + r * 296 + c, wq + (size_t)r * 288 + c);
            }
        }
        CP_COMMIT();
    }

    for (int it = 0; it < 6; it++) {
        int buf = it & 1;
        if (it < 5) {
            int kb = (it + 1) * 16, nb = buf ^ 1;
            cpa16(sAb[nb] + ar * 20 + ac, A + (size_t)(row0 + ar) * 96 + kb + ac);
#pragma unroll
            for (int i = 0; i < 5; i++) {
                int idx = tid + i * 256;
                if (idx < 1152) {
                    int r = idx / 72, c = (idx % 72) * 4;
                    cpa16(sWb[nb] + r * 296 + c, wq + (size_t)(kb + r) * 288 + c);
                }
            }
            CP_COMMIT();
            CP_WAIT1();
        } else {
            CP_WAIT0();
        }
        __syncthreads();
        const float* sA = sAb[buf];
        const float* sW = sWb[buf];
#pragma unroll
        for (int sk = 0; sk < 16; sk += 8) {
            unsigned a0[2], a1[2], a2[2], a3[2];
#pragma unroll
            for (int mt = 0; mt < 2; mt++) {
                int r = mrow + mt * 16;
                a0[mt] = __float_as_uint(sA[(r + g) * 20 + sk + t]);
                a1[mt] = __float_as_uint(sA[(r + g + 8) * 20 + sk + t]);
                a2[mt] = __float_as_uint(sA[(r + g) * 20 + sk + t + 4]);
                a3[mt] = __float_as_uint(sA[(r + g + 8) * 20 + sk + t + 4]);
            }
#pragma unroll
            for (int j = 0; j < 9; j++) {
                int n0 = wn * 72 + j * 8;
                unsigned b0v = __float_as_uint(sW[(sk + t) * 296 + n0 + g]);
                unsigned b1v = __float_as_uint(sW[(sk + t + 4) * 296 + n0 + g]);
                mma8(acc[0][j], a0[0], a1[0], a2[0], a3[0], b0v, b1v);
                mma8(acc[1][j], a0[1], a1[1], a2[1], a3[1], b0v, b1v);
            }
        }
        __syncthreads();
    }
    float* Q = g_pool + OF_QKV + (size_t)blockIdx.x * 18432;
    const float* gate = g_pool + OF_GATE + (blockIdx.x >> 9) * 96;
#pragma unroll
    for (int mt = 0; mt < 2; mt++) {
        int n0r = mrow + mt * 16 + g, n1r = n0r + 8;
#pragma unroll
        for (int j = 0; j < 9; j++) {
            int c = wn * 72 + j * 8 + 2 * t;
            int s = c / 96, rem = c - s * 96, h = rem >> 4, d = rem & 15;
            float bx = qb[c], by = qb[c + 1];
            float x0 = acc[mt][j].x + bx, y0 = acc[mt][j].y + by;
            float z0 = acc[mt][j].z + bx, w0 = acc[mt][j].w + by;
            if (s == 0) { x0 *= 0.25f; y0 *= 0.25f; z0 *= 0.25f; w0 *= 0.25f; }
            else if (s == 2) {
                float g0 = gate[rem], g1 = gate[rem + 1];
                x0 *= g0; y0 *= g1; z0 *= g0; w0 *= g1;
            }
            float* dst = Q + s * 6144 + h * 1024 + d;
            *(float2*)(dst + n0r * 16) = make_float2(x0, y0);
            *(float2*)(dst + n1r * 16) = make_float2(z0, w0);
        }
    }
}

// ============================================================
// K7b: attention per window (vectorized smem, pad 20)
// ============================================================
__global__ __launch_bounds__(256) void k_attn()
{
    __shared__ float qS[64][20], kS[64][20], vS[64][20];
    __shared__ float pS[64][65];
    int tid = threadIdx.x;
    int win = blockIdx.x;
    const float* qkv = g_pool + OF_QKV + (size_t)win * 18432;
    const float* biasT = g_pool + OF_BIAS;
    float* out = g_pool + OF_AOUT + (size_t)win * 64 * 96;
    int warp = tid >> 5, lane = tid & 31;
    int sn = tid >> 2, sd = (tid & 3) * 4;

    for (int hh = 0; hh < 6; hh++) {
        {
            const float* base = qkv + hh * 1024 + sn * 16 + sd;
            *(float4*)&qS[sn][sd] = *(const float4*)(base);
            *(float4*)&kS[sn][sd] = *(const float4*)(base + 6144);
            *(float4*)&vS[sn][sd] = *(const float4*)(base + 12288);
        }
        __syncthreads();
        for (int rr = 0; rr < 8; rr++) {
            int n = warp * 8 + rr;
            int m0 = lane, m1 = lane + 32;
            float s0 = biasT[hh * 4096 + n * 64 + m0];
            float s1 = biasT[hh * 4096 + n * 64 + m1];
#pragma unroll
            for (int d4 = 0; d4 < 4; d4++) {
                float4 qv = *(const float4*)&qS[n][d4 * 4];
                float4 k0 = *(const float4*)&kS[m0][d4 * 4];
                float4 k1 = *(const float4*)&kS[m1][d4 * 4];
                s0 += qv.x * k0.x + qv.y * k0.y + qv.z * k0.z + qv.w * k0.w;
                s1 += qv.x * k1.x + qv.y * k1.y + qv.z * k1.z + qv.w * k1.w;
            }
            float mx = fmaxf(s0, s1);
#pragma unroll
            for (int o = 16; o; o >>= 1) mx = fmaxf(mx, __shfl_xor_sync(~0u, mx, o));
            float e0 = expf(s0 - mx), e1 = expf(s1 - mx);
            float sum = e0 + e1;
#pragma unroll
            for (int o = 16; o; o >>= 1) sum += __shfl_xor_sync(~0u, sum, o);
            float inv = 1.f / sum;
            pS[n][m0] = e0 * inv;
            pS[n][m1] = e1 * inv;
        }
        __syncthreads();
        {
            int n = tid >> 2, dg = tid & 3;
            float a0 = 0.f, a1 = 0.f, a2 = 0.f, a3 = 0.f;
#pragma unroll
            for (int m = 0; m < 64; m++) {
                float pm = pS[n][m];
                float4 v = *(const float4*)&vS[m][dg * 4];
                a0 += pm * v.x; a1 += pm * v.y; a2 += pm * v.z; a3 += pm * v.w;
            }
            size_t ob = (size_t)n * 96 + hh * 16 + dg * 4;
            *(float4*)(out + ob) = make_float4(a0, a1, a2, a3);
        }
        __syncthreads();
    }
}

// ============================================================
// K8a: si stage 1
// ============================================================
__global__ __launch_bounds__(256) void k_si1(
    const float* __restrict__ w1, const float* __restrict__ b1)
{
    __shared__ float aS[64][97];
    __shared__ float wS[96 * 12];
    __shared__ float sb[64][12];
    int tid = threadIdx.x;
    int blk = blockIdx.x; int row0 = blk * 64;
    const float* A = g_pool + OF_AOUT;
    for (int i = tid; i < 96 * 12; i += 256) wS[i] = w1[i];
    for (int i = tid; i < 64 * 96; i += 256) {
        int r = i / 96, c = i % 96;
        aS[r][c] = A[(size_t)(row0 + r) * 96 + c];
    }
    __syncthreads();
    {
        int r = tid >> 2, jg = tid & 3;
        float s0 = b1[jg * 3 + 0], s1 = b1[jg * 3 + 1], s2 = b1[jg * 3 + 2];
        for (int c = 0; c < 96; c++) {
            float a = aS[r][c];
            s0 += a * wS[c * 12 + jg * 3 + 0];
            s1 += a * wS[c * 12 + jg * 3 + 1];
            s2 += a * wS[c * 12 + jg * 3 + 2];
        }
        float* o = g_pool + OF_S12 + (size_t)(row0 + r) * 12 + jg * 3;
        o[0] = s0; o[1] = s1; o[2] = s2;
        sb[r][jg * 3 + 0] = s0; sb[r][jg * 3 + 1] = s1; sb[r][jg * 3 + 2] = s2;
    }
    __syncthreads();
    if (tid < 12) {
        float S = 0.f, Q = 0.f;
        for (int r = 0; r < 64; r++) { float v = sb[r][tid]; S += v; Q += v * v; }
        g_pool[OF_P12S + (size_t)blk * 12 + tid] = S;
        g_pool[OF_P12Q + (size_t)blk * 12 + tid] = Q;
    }
}

// ============================================================
// K8c: gate + multiply + partials
// ============================================================
__global__ __launch_bounds__(96) void k_gatemul(
    const float* __restrict__ w2, const float* __restrict__ b2)
{
    __shared__ float gb[64];
    int tid = threadIdx.x;
    int blk = blockIdx.x; int row0 = blk * 64; int b = row0 >> 15;
    if (tid < 64) {
        const float* s = g_pool + OF_S12 + (size_t)(row0 + tid) * 12;
        float a = b2[0];
#pragma unroll
        for (int j = 0; j < 12; j++) {
            float v = (s[j] - g_pool[OF_M2 + b * 12 + j]) * g_pool[OF_R2 + b * 12 + j];
            a += geluf(v) * w2[j];
        }
        gb[tid] = 1.f / (1.f + expf(-a));
    }
    __syncthreads();
    const float* vp = g_pool + OF_VOLP + (size_t)row0 * 96 + tid;
    float* yv = g_pool + OF_YV + (size_t)row0 * 96 + tid;
    float ss = 0.f, sq = 0.f;
    for (int r = 0; r < 64; r++) {
        float y = gb[r] * vp[(size_t)r * 96];
        yv[(size_t)r * 96] = y;
        ss += y; sq += y * y;
    }
    g_pool[OF_PYS + (size_t)blk * 96 + tid] = ss;
    g_pool[OF_PYQ + (size_t)blk * 96 + tid] = sq;
}

// ============================================================
// K9: final (tf32 mma, K-chunk 16 double-buffered W, 3 CTA/SM)
// ============================================================
__global__ __launch_bounds__(256, 3) void k_final(
    const float* __restrict__ bp,
    const float* __restrict__ ga, const float* __restrict__ ba,
    float* __restrict__ out)
{
    extern __shared__ float sm[];
    float (*sA)[196] = (float(*)[196])sm;
    float* sWb[2] = { sm + 12544, sm + 12544 + 3200 };
    const float* wp = g_pool + OF_WPROJ;
    const int tid = threadIdx.x, warp = tid >> 5, lane = tid & 31;
    const int g = lane >> 2, t = lane & 3;
    const int wm = warp >> 2, wn = warp & 3;
    const int row0 = blockIdx.x * 64; const int b = row0 >> 15;
    const int mrow = wm * 32;
    const float* A = g_pool + OF_AOUT;
    const float* Y = g_pool + OF_YV;

    {
#pragma unroll
        for (int i = 0; i < 3; i++) {
            int idx = tid + i * 256; int r = idx / 48, c = (idx % 48) * 4;
            cpa16(sWb[0] + r * 200 + c, wp + (size_t)r * 192 + c);
        }
        CP_COMMIT();
    }

    for (int it = 0; it < 8; it++) {
        int r = warp * 8 + it;
        int row = row0 + r;
        float s = 0.f, q = 0.f;
        float vals[3];
#pragma unroll
        for (int i = 0; i < 3; i++) {
            vals[i] = A[(size_t)row * 96 + lane + 32 * i];
            s += vals[i]; q += vals[i] * vals[i];
        }
#pragma unroll
        for (int o = 16; o; o >>= 1) { s += __shfl_xor_sync(~0u, s, o); q += __shfl_xor_sync(~0u, q, o); }
        float m = s * (1.f / 96.f);
        float rs = rsqrtf(fmaxf(q * (1.f / 96.f) - m * m, 0.f) + EPS);
#pragma unroll
        for (int i = 0; i < 3; i++) {
            int c = lane + 32 * i;
            sA[r][c] = tf32f((vals[i] - m) * rs * ga[c] + ba[c]);
        }
#pragma unroll
        for (int i = 0; i < 3; i++) {
            int c = lane + 32 * i;
            float v = (Y[(size_t)row * 96 + c] - g_pool[OF_M3 + b * 96 + c]) * g_pool[OF_R3 + b * 96 + c];
            sA[r][96 + c] = tf32f(v);
        }
    }
    __syncthreads();

    float4 acc[2][6];
#pragma unroll
    for (int mt = 0; mt < 2; mt++)
#pragma unroll
        for (int j = 0; j < 6; j++) acc[mt][j] = make_float4(0.f, 0.f, 0.f, 0.f);

    for (int it = 0; it < 12; it++) {
        int buf = it & 1;
        int kb = it * 16;
        if (it < 11) {
            int nkb = kb + 16, nb = buf ^ 1;
#pragma unroll
            for (int i = 0; i < 3; i++) {
                int idx = tid + i * 256; int r = idx / 48, c = (idx % 48) * 4;
                cpa16(sWb[nb] + r * 200 + c, wp + (size_t)(nkb + r) * 192 + c);
            }
            CP_COMMIT();
            CP_WAIT1();
        } else {
            CP_WAIT0();
        }
        __syncthreads();
        const float* sW = sWb[buf];
#pragma unroll
        for (int sk = 0; sk < 16; sk += 8) {
            unsigned a0[2], a1[2], a2[2], a3[2];
#pragma unroll
            for (int mt = 0; mt < 2; mt++) {
                int r = mrow + mt * 16;
                a0[mt] = __float_as_uint(sA[r + g][kb + sk + t]);
                a1[mt] = __float_as_uint(sA[r + g + 8][kb + sk + t]);
                a2[mt] = __float_as_uint(sA[r + g][kb + sk + t + 4]);
                a3[mt] = __float_as_uint(sA[r + g + 8][kb + sk + t + 4]);
            }
#pragma unroll
            for (int j = 0; j < 6; j++) {
                int n0 = wn * 48 + j * 8;
                unsigned b0v = __float_as_uint(sW[(sk + t) * 200 + n0 + g]);
                unsigned b1v = __float_as_uint(sW[(sk + t + 4) * 200 + n0 + g]);
                mma8(acc[0][j], a0[0], a1[0], a2[0], a3[0], b0v, b1v);
                mma8(acc[1][j], a0[1], a1[1], a2[1], a3[1], b0v, b1v);
            }
        }
        __syncthreads();
    }
#pragma unroll
    for (int mt = 0; mt < 2; mt++) {
        int r0 = row0 + mrow + mt * 16 + g, r1 = r0 + 8;
#pragma unroll
        for (int j = 0; j < 6; j++) {
            int c = wn * 48 + j * 8 + 2 * t;
            float bx = bp[c], by = bp[c + 1];
            *(float2*)&out[(size_t)r0 * 192 + c] = make_float2(acc[mt][j].x + bx, acc[mt][j].y + by);
            *(float2*)&out[(size_t)r1 * 192 + c] = make_float2(acc[mt][j].z + bx, acc[mt][j].w + by);
        }
    }
}

// ============================================================
// host launcher
// ============================================================
extern "C" void kernel_launch(void* const* d_in, const int* in_sizes, int n_in,
                              void* d_out, int out_size)
{
    const float* x       = (const float*)d_in[0];
    const float* w_pattn = (const float*)d_in[1];
    const float* b_pattn = (const float*)d_in[2];
    const float* g_aln   = (const float*)d_in[3];
    const float* b_aln   = (const float*)d_in[4];
    const float* w_pcnn  = (const float*)d_in[5];
    const float* b_pcnn  = (const float*)d_in[6];
    const float* g_cln   = (const float*)d_in[7];
    const float* b_cln   = (const float*)d_in[8];
    const float* dw_w    = (const float*)d_in[9];
    const float* dw_b    = (const float*)d_in[10];
    const float* ci_w1   = (const float*)d_in[11];
    const float* ci_b1   = (const float*)d_in[12];
    const float* ci_w2   = (const float*)d_in[13];
    const float* ci_b2   = (const float*)d_in[14];
    const float* pj_w    = (const float*)d_in[15];
    const float* pj_b    = (const float*)d_in[16];
    const float* qkv_w   = (const float*)d_in[17];
    const float* qkv_b   = (const float*)d_in[18];
    const float* si_w1   = (const float*)d_in[19];
    const float* si_b1   = (const float*)d_in[20];
    const float* si_w2   = (const float*)d_in[21];
    const float* si_b2   = (const float*)d_in[22];
    const float* g_anorm = (const float*)d_in[23];
    const float* b_anorm = (const float*)d_in[24];
    const float* w_proj  = (const float*)d_in[25];
    const float* b_proj  = (const float*)d_in[26];
    const float* rpb     = (const float*)d_in[27];

    const int Bwin = in_sizes[0] / (64 * 192);   // 2048
    const int rows = Bwin * 64;                  // 131072
    const int nb   = Bwin / 512;                 // 4

    cudaFuncSetAttribute(k_embed, cudaFuncAttributeMaxDynamicSharedMemorySize, 75776);
    cudaFuncSetAttribute(k_qkv,   cudaFuncAttributeMaxDynamicSharedMemorySize, 50176);
    cudaFuncSetAttribute(k_final, cudaFuncAttributeMaxDynamicSharedMemorySize, 77824);

    // k_dwconv at launch index 3 (ncu capture slot)
    k_wprep<<<216, 256>>>(w_pattn, w_pcnn, qkv_w, w_proj, pj_w);
    k_bias<<<6, 256>>>(rpb);
    k_embed<<<rows / 64, 256, 73728>>>(x, b_pattn, g_aln, b_aln,
                                       b_pcnn, g_cln, b_cln);
    k_dwconv<<<nb * 1024, 192>>>(dw_w, dw_b);
    k_redstats<<<nb * 192, 128>>>(OF_PCS, OF_PCQ, 1024, 192, 1.f / 32768.f, OF_M1, OF_R1);
    k_pool<<<nb * 1024, 192>>>();
    k_redmean<<<nb * 192, 128>>>(OF_PPOOL, 1024, 192, 1.f / 32768.f, OF_POOLED);
    k_ci<<<1, 96>>>(ci_w1, ci_b1, ci_w2, ci_b2, nb);
    k_pj<<<rows / 64, 256>>>(pj_b);
    k_qkv<<<rows / 64, 256, 48128>>>(qkv_b);
    k_attn<<<Bwin, 256>>>();
    k_si1<<<rows / 64, 256>>>(si_w1, si_b1);
    k_redstats<<<nb * 12, 128>>>(OF_P12S, OF_P12Q, 512, 12, 1.f / 32768.f, OF_M2, OF_R2);
    k_gatemul<<<rows / 64, 96>>>(si_w2, si_b2);
    k_redstats<<<nb * 96, 128>>>(OF_PYS, OF_PYQ, 512, 96, 1.f / 32768.f, OF_M3, OF_R3);
    k_final<<<rows / 64, 256, 75776>>>(b_proj, g_anorm, b_anorm, (float*)d_out);
}

// round 17
// speedup vs baseline: 1.0591x; 1.0109x over previous
#include <cuda_runtime.h>
#include <math.h>

#define EPS 1e-5f

// ---------------- scratch pool (floats) ----------------
#define OF_VOLA   0ull
#define OF_VOLB   25165824ull
#define OF_QKV    50331648ull
#define OF_XATT   88080384ull
#define OF_AOUT   100663296ull
#define OF_VOLP   113246208ull
#define OF_YV     125829120ull
#define OF_S12    138412032ull
#define OF_PCS    139984896ull
#define OF_PCQ    140771328ull
#define OF_PPOOL  141557760ull
#define OF_P12S   142344192ull
#define OF_P12Q   142368768ull
#define OF_PYS    142393344ull
#define OF_PYQ    142589952ull
#define OF_M1     142786560ull
#define OF_R1     142787328ull
#define OF_POOLED 142788096ull
#define OF_M2     142788864ull
#define OF_R2     142788912ull
#define OF_M3     142788960ull
#define OF_R3     142789344ull
#define OF_GATE   142789728ull
#define OF_BIAS   142790144ull   // 24576
#define OF_WEMB   142814720ull   // 192*288 = 55296
#define OF_WQKV   142870016ull   // 96*288  = 27648
#define OF_WPROJ  142897664ull   // 192*192 = 36864
#define OF_WPJ    142934528ull   // 192*96  = 18432
#define OF_ZROW   142952960ull   // 6144 zeros (32*192)

__device__ float g_pool[143000000];

__device__ __forceinline__ float geluf(float x) {
    return 0.5f * x * (1.0f + erff(x * 0.70710678118654752f));
}

__device__ __forceinline__ float tf32f(float x) {
    unsigned u;
    asm("cvt.rna.tf32.f32 %0, %1;" : "=r"(u) : "f"(x));
    return __uint_as_float(u);
}

__device__ __forceinline__ void cpa16(float* dst, const float* src) {
    unsigned d = (unsigned)__cvta_generic_to_shared(dst);
    asm volatile("cp.async.ca.shared.global [%0], [%1], 16;" :: "r"(d), "l"(src));
}
#define CP_COMMIT() asm volatile("cp.async.commit_group;")
#define CP_WAIT1()  asm volatile("cp.async.wait_group 1;")
#define CP_WAIT0()  asm volatile("cp.async.wait_group 0;")

__device__ __forceinline__ void mma8(float4& d, unsigned a0, unsigned a1,
                                     unsigned a2, unsigned a3,
                                     unsigned b0, unsigned b1) {
    asm volatile(
        "mma.sync.aligned.m16n8k8.row.col.f32.tf32.tf32.f32 "
        "{%0,%1,%2,%3},{%4,%5,%6,%7},{%8,%9},{%0,%1,%2,%3};"
        : "+f"(d.x), "+f"(d.y), "+f"(d.z), "+f"(d.w)
        : "r"(a0), "r"(a1), "r"(a2), "r"(a3), "r"(b0), "r"(b1));
}

__device__ __forceinline__ int spatial_of_row(int row) {
    int win = row >> 6, n = row & 63;
    int b = win >> 9, d = (win >> 6) & 7, h = (win >> 3) & 7, w = win & 7;
    int wd = n >> 4, wh = (n >> 2) & 3, ww = n & 3;
    int Z = d * 4 + wd, Y = h * 4 + wh, X = w * 4 + ww;
    return ((b * 32 + Z) * 32 + Y) * 32 + X;
}

// ============================================================
// K-1: one-off weight prep: tf32-round all GEMM weights + zero stripe
// ============================================================
__global__ __launch_bounds__(256) void k_wprep(
    const float* __restrict__ w1, const float* __restrict__ w2,
    const float* __restrict__ qw, const float* __restrict__ pw,
    const float* __restrict__ jw)
{
    int i = blockIdx.x * 256 + threadIdx.x;
    if (i < 55296) {
        int k = i / 288, c = i % 288;
        float v = (c < 96) ? w1[k * 96 + c] : w2[k * 192 + (c - 96)];
        g_pool[OF_WEMB + i] = tf32f(v);
    }
    if (i < 27648) g_pool[OF_WQKV + i] = tf32f(qw[i]);
    if (i < 36864) g_pool[OF_WPROJ + i] = tf32f(pw[i]);
    if (i < 18432) g_pool[OF_WPJ + i] = tf32f(jw[i]);
    if (i < 6144)  g_pool[OF_ZROW + i] = 0.f;
}

// ============================================================
// K0: precompute rel-pos bias table
// ============================================================
__global__ __launch_bounds__(256) void k_bias(const float* __restrict__ rpb)
{
    int hh = blockIdx.x;
    for (int p = threadIdx.x; p < 4096; p += 256) {
        int n = p >> 6, m = p & 63;
        int nd = n >> 4, nh = (n >> 2) & 3, nw = n & 3;
        int md = m >> 4, mh = (m >> 2) & 3, mw = m & 3;
        int idx = ((nd - md + 3) * 49 + (nh - mh + 3) * 7 + (nw - mw + 3)) * 6 + hh;
        g_pool[OF_BIAS + hh * 4096 + p] = rpb[idx];
    }
}

// ============================================================
// K1: embed GEMM, K-chunk 16 double-buffered
// ============================================================
__global__ __launch_bounds__(256) void k_embed(
    const float* __restrict__ x, const float* __restrict__ b1,
    const float* __restrict__ ga, const float* __restrict__ ba,
    const float* __restrict__ b2,
    const float* __restrict__ gc, const float* __restrict__ bc)
{
    extern __shared__ float sm[];
    float* sAb[2] = { sm, sm + 1280 };
    float* sWb[2] = { sm + 2560, sm + 2560 + 4736 };
    float (*sOut)[288] = (float(*)[288])sm;
    const float* wemb = g_pool + OF_WEMB;
    const int tid = threadIdx.x, warp = tid >> 5, lane = tid & 31;
    const int g = lane >> 2, t = lane & 3;
    const int wm = warp >> 2, wn = warp & 3;
    const int row0 = blockIdx.x * 64;
    const int mrow = wm * 32;
    const int ar = tid >> 2, ac = (tid & 3) * 4;

    float4 acc[2][9];
#pragma unroll
    for (int mt = 0; mt < 2; mt++)
#pragma unroll
        for (int j = 0; j < 9; j++) acc[mt][j] = make_float4(0.f, 0.f, 0.f, 0.f);

    {
        cpa16(sAb[0] + ar * 20 + ac, x + (size_t)(row0 + ar) * 192 + ac);
#pragma unroll
        for (int i = 0; i < 5; i++) {
            int idx = tid + i * 256;
            if (idx < 1152) {
                int r = idx / 72, c = (idx % 72) * 4;
                cpa16(sWb[0] + r * 296 + c, wemb + (size_t)r * 288 + c);
            }
        }
        CP_COMMIT();
    }

    for (int it = 0; it < 12; it++) {
        int buf = it & 1;
        if (it < 11) {
            int kb = (it + 1) * 16, nb = buf ^ 1;
            cpa16(sAb[nb] + ar * 20 + ac, x + (size_t)(row0 + ar) * 192 + kb + ac);
#pragma unroll
            for (int i = 0; i < 5; i++) {
                int idx = tid + i * 256;
                if (idx < 1152) {
                    int r = idx / 72, c = (idx % 72) * 4;
                    cpa16(sWb[nb] + r * 296 + c, wemb + (size_t)(kb + r) * 288 + c);
                }
            }
            CP_COMMIT();
            CP_WAIT1();
        } else {
            CP_WAIT0();
        }
        __syncthreads();
        const float* sA = sAb[buf];
        const float* sW = sWb[buf];
#pragma unroll
        for (int sk = 0; sk < 16; sk += 8) {
            unsigned a0[2], a1[2], a2[2], a3[2];
#pragma unroll
            for (int mt = 0; mt < 2; mt++) {
                int r = mrow + mt * 16;
                a0[mt] = __float_as_uint(tf32f(sA[(r + g) * 20 + sk + t]));
                a1[mt] = __float_as_uint(tf32f(sA[(r + g + 8) * 20 + sk + t]));
                a2[mt] = __float_as_uint(tf32f(sA[(r + g) * 20 + sk + t + 4]));
                a3[mt] = __float_as_uint(tf32f(sA[(r + g + 8) * 20 + sk + t + 4]));
            }
#pragma unroll
            for (int j = 0; j < 9; j++) {
                int n0 = wn * 72 + j * 8;
                unsigned b0v = __float_as_uint(sW[(sk + t) * 296 + n0 + g]);
                unsigned b1v = __float_as_uint(sW[(sk + t + 4) * 296 + n0 + g]);
                mma8(acc[0][j], a0[0], a1[0], a2[0], a3[0], b0v, b1v);
                mma8(acc[1][j], a0[1], a1[1], a2[1], a3[1], b0v, b1v);
            }
        }
        __syncthreads();
    }
#pragma unroll
    for (int mt = 0; mt < 2; mt++) {
        int r0 = mrow + mt * 16 + g, r1 = r0 + 8;
#pragma unroll
        for (int j = 0; j < 9; j++) {
            int c = wn * 72 + j * 8 + 2 * t;
            float bx = (c < 96) ? b1[c] : b2[c - 96];
            float by = (c + 1 < 96) ? b1[c + 1] : b2[c + 1 - 96];
            sOut[r0][c] = acc[mt][j].x + bx; sOut[r0][c + 1] = acc[mt][j].y + by;
            sOut[r1][c] = acc[mt][j].z + bx; sOut[r1][c + 1] = acc[mt][j].w + by;
        }
    }
    __syncthreads();

    for (int r = warp; r < 64; r += 8) {
        int row = row0 + r;
        float s = 0.f, q = 0.f;
#pragma unroll
        for (int i = 0; i < 3; i++) { float v = sOut[r][lane + 32 * i]; s += v; q += v * v; }
#pragma unroll
        for (int o = 16; o; o >>= 1) { s += __shfl_xor_sync(~0u, s, o); q += __shfl_xor_sync(~0u, q, o); }
        float m = s * (1.f / 96.f);
        float rs = rsqrtf(fmaxf(q * (1.f / 96.f) - m * m, 0.f) + EPS);
        float* xao = g_pool + OF_XATT + (size_t)row * 96;
#pragma unroll
        for (int i = 0; i < 3; i++) {
            int c = lane + 32 * i;
            xao[c] = tf32f((sOut[r][c] - m) * rs * ga[c] + ba[c]);
        }
        s = 0.f; q = 0.f;
#pragma unroll
        for (int i = 0; i < 6; i++) { float v = sOut[r][96 + lane + 32 * i]; s += v; q += v * v; }
#pragma unroll
        for (int o = 16; o; o >>= 1) { s += __shfl_xor_sync(~0u, s, o); q += __shfl_xor_sync(~0u, q, o); }
        m = s * (1.f / 192.f);
        rs = rsqrtf(fmaxf(q * (1.f / 192.f) - m * m, 0.f) + EPS);
        float* va = g_pool + OF_VOLA + (size_t)spatial_of_row(row) * 192;
#pragma unroll
        for (int i = 0; i < 6; i++) {
            int c = lane + 32 * i;
            va[c] = (sOut[r][96 + c] - m) * rs * gc[c] + bc[c];
        }
    }
}

// ============================================================
// K2: depthwise conv 3x3x3 + bias, partial stats
// zero-stripe bases, scatter-accumulate, 2 y-rows per block
// ============================================================
__global__ __launch_bounds__(192, 3) void k_dwconv(
    const float* __restrict__ dww, const float* __restrict__ dwb)
{
    const float* vin = g_pool + OF_VOLA;
    float* vout = g_pool + OF_VOLB;
    int c = threadIdx.x;
    int blk = blockIdx.x;                 // nb*512 blocks
    int b = blk >> 9, z = (blk >> 4) & 31, y0 = (blk & 15) * 2;

    float w[27];
#pragma unroll
    for (int i = 0; i < 27; i++) w[i] = dww[c * 27 + i];
    float bias = dwb[c];

    const float* base[12];                // [dz][dy4], dy4 = y0-1+dy4
#pragma unroll
    for (int dz = 0; dz < 3; dz++)
#pragma unroll
        for (int dy = 0; dy < 4; dy++) {
            int l = dz * 4 + dy;
            int zz = z + dz - 1, yy = y0 + dy - 1;
            bool ok = (zz >= 0 && zz < 32 && yy >= 0 && yy < 32);
            base[l] = ok ? (vin + ((size_t)((b * 32 + zz) * 32 + yy) * 32) * 192 + c)
                         : (g_pool + OF_ZROW + c);
        }

    float colA[12], colB[12];
#pragma unroll
    for (int l = 0; l < 12; l++) colA[l] = base[l][0];

    float accA0 = 0.f, accB0 = bias;
    float accA1 = 0.f, accB1 = bias;
    float ss0 = 0.f, sq0 = 0.f, ss1 = 0.f, sq1 = 0.f;
    int rowidx = ((b * 32 + z) * 32 + y0);
    float* orow0 = vout + ((size_t)rowidx * 32) * 192 + c;
    float* orow1 = orow0 + 32 * 192;

#pragma unroll 2
    for (int cx = 0; cx < 32; cx++) {
        float* cur = (cx & 1) ? colB : colA;
        float* nxt = (cx & 1) ? colA : colB;
        if (cx < 31) {
#pragma unroll
            for (int l = 0; l < 12; l++) nxt[l] = base[l][(cx + 1) * 192];
        }
        float s2a = 0.f, s1a = 0.f, s0a = 0.f;
        float s2b = 0.f, s1b = 0.f, s0b = 0.f;
#pragma unroll
        for (int dz = 0; dz < 3; dz++)
#pragma unroll
            for (int dy = 0; dy < 3; dy++) {
                int wl = (dz * 3 + dy) * 3;
                float v0 = cur[dz * 4 + dy];
                float v1 = cur[dz * 4 + dy + 1];
                s2a += w[wl + 2] * v0; s1a += w[wl + 1] * v0; s0a += w[wl + 0] * v0;
                s2b += w[wl + 2] * v1; s1b += w[wl + 1] * v1; s0b += w[wl + 0] * v1;
            }
        accA0 += s2a; accB0 += s1a; float accC0 = bias + s0a;
        accA1 += s2b; accB1 += s1b; float accC1 = bias + s0b;
        if (cx >= 1) {
            orow0[(cx - 1) * 192] = accA0; ss0 += accA0; sq0 += accA0 * accA0;
            orow1[(cx - 1) * 192] = accA1; ss1 += accA1; sq1 += accA1 * accA1;
        }
        accA0 = accB0; accB0 = accC0;
        accA1 = accB1; accB1 = accC1;
    }
    orow0[31 * 192] = accA0; ss0 += accA0; sq0 += accA0 * accA0;
    orow1[31 * 192] = accA1; ss1 += accA1; sq1 += accA1 * accA1;

    g_pool[OF_PCS + (size_t)rowidx * 192 + c] = ss0;
    g_pool[OF_PCQ + (size_t)rowidx * 192 + c] = sq0;
    g_pool[OF_PCS + (size_t)(rowidx + 1) * 192 + c] = ss1;
    g_pool[OF_PCQ + (size_t)(rowidx + 1) * 192 + c] = sq1;
}

// ============================================================
// reductions
// ============================================================
__global__ __launch_bounds__(128) void k_redstats(
    unsigned long long ofs, unsigned long long ofq, int nchunk, int C, float invN,
    unsigned long long ofm, unsigned long long ofr)
{
    __shared__ float ss[128], qq[128];
    int g = blockIdx.x; int b = g / C, c = g % C;
    float s = 0.f, q = 0.f;
    for (int i = threadIdx.x; i < nchunk; i += 128) {
        size_t o = ((size_t)b * nchunk + i) * C + c;
        s += g_pool[ofs + o]; q += g_pool[ofq + o];
    }
    ss[threadIdx.x] = s; qq[threadIdx.x] = q; __syncthreads();
    for (int o = 64; o; o >>= 1) {
        if (threadIdx.x < o) { ss[threadIdx.x] += ss[threadIdx.x + o]; qq[threadIdx.x] += qq[threadIdx.x + o]; }
        __syncthreads();
    }
    if (threadIdx.x == 0) {
        float m = ss[0] * invN;
        g_pool[ofm + g] = m;
        g_pool[ofr + g] = rsqrtf(fmaxf(qq[0] * invN - m * m, 0.f) + EPS);
    }
}

__global__ __launch_bounds__(128) void k_redmean(
    unsigned long long ofs, int nchunk, int C, float invN, unsigned long long ofm)
{
    __shared__ float ss[128];
    int g = blockIdx.x; int b = g / C, c = g % C;
    float s = 0.f;
    for (int i = threadIdx.x; i < nchunk; i += 128)
        s += g_pool[ofs + ((size_t)b * nchunk + i) * C + c];
    ss[threadIdx.x] = s; __syncthreads();
    for (int o = 64; o; o >>= 1) {
        if (threadIdx.x < o) ss[threadIdx.x] += ss[threadIdx.x + o];
        __syncthreads();
    }
    if (threadIdx.x == 0) g_pool[ofm + g] = ss[0] * invN;
}

// ============================================================
// K4: pooled partials only
// ============================================================
__global__ __launch_bounds__(192) void k_pool()
{
    int c = threadIdx.x;
    int blk = blockIdx.x; int b = blk >> 10;
    float m = g_pool[OF_M1 + b * 192 + c], rs = g_pool[OF_R1 + b * 192 + c];
    const float* v = g_pool + OF_VOLB + ((size_t)blk * 32) * 192 + c;
    float s = 0.f;
    for (int xx = 0; xx < 32; xx++)
        s += geluf((v[(size_t)xx * 192] - m) * rs);
    g_pool[OF_PPOOL + (size_t)blk * 192 + c] = s;
}

// ============================================================
// K5: ci MLP
// ============================================================
__global__ __launch_bounds__(96) void k_ci(
    const float* __restrict__ w1, const float* __restrict__ b1,
    const float* __restrict__ w2, const float* __restrict__ b2, int nb)
{
    __shared__ float t24[24];
    int tid = threadIdx.x;
    for (int b = 0; b < nb; b++) {
        if (tid < 24) {
            float s = b1[tid];
            for (int c = 0; c < 192; c++) s += g_pool[OF_POOLED + b * 192 + c] * w1[c * 24 + tid];
            t24[tid] = geluf(s);
        }
        __syncthreads();
        {
            float s = b2[tid];
#pragma unroll
            for (int j = 0; j < 24; j++) s += t24[j] * w2[j * 96 + tid];
            g_pool[OF_GATE + b * 96 + tid] = 1.f / (1.f + expf(-s));
        }
        __syncthreads();
    }
}

// ============================================================
// K6: pj conv1x1 (pre-tf32 W, fused inorm+gelu A)
// ============================================================
__global__ __launch_bounds__(256) void k_pj(const float* __restrict__ pb)
{
    __shared__ float sA[64][36];
    __shared__ float sW[32][104];
    const int tid = threadIdx.x, warp = tid >> 5, lane = tid & 31;
    const int g = lane >> 2, t = lane & 3;
    const int wm = warp >> 2, wn = warp & 3;
    const int row0 = blockIdx.x * 64;
    const int b = row0 >> 15;
    const int mrow = wm * 32;
    const float* vb = g_pool + OF_VOLB;
    const float* wpj = g_pool + OF_WPJ;
    const float* M1 = g_pool + OF_M1 + b * 192;
    const float* R1 = g_pool + OF_R1 + b * 192;

    float4 acc[2][3];
#pragma unroll
    for (int mt = 0; mt < 2; mt++)
#pragma unroll
        for (int j = 0; j < 3; j++) acc[mt][j] = make_float4(0.f, 0.f, 0.f, 0.f);

    for (int kb = 0; kb < 192; kb += 32) {
#pragma unroll
        for (int i = 0; i < 2; i++) {
            int idx = tid * 2 + i; int r = idx >> 3, c = (idx & 7) * 4;
            float4 v = *(const float4*)(vb + (size_t)spatial_of_row(row0 + r) * 192 + kb + c);
            int ch = kb + c;
            sA[r][c]     = tf32f(geluf((v.x - M1[ch])     * R1[ch]));
            sA[r][c + 1] = tf32f(geluf((v.y - M1[ch + 1]) * R1[ch + 1]));
            sA[r][c + 2] = tf32f(geluf((v.z - M1[ch + 2]) * R1[ch + 2]));
            sA[r][c + 3] = tf32f(geluf((v.w - M1[ch + 3]) * R1[ch + 3]));
        }
#pragma unroll
        for (int i = 0; i < 3; i++) {
            int idx = tid + i * 256; int r = idx / 24, c = (idx % 24) * 4;
            *(float4*)&sW[r][c] = *(const float4*)(wpj + (size_t)(kb + r) * 96 + c);
        }
        __syncthreads();
#pragma unroll
        for (int sk = 0; sk < 32; sk += 8) {
            unsigned a0[2], a1[2], a2[2], a3[2];
#pragma unroll
            for (int mt = 0; mt < 2; mt++) {
                int r = mrow + mt * 16;
                a0[mt] = __float_as_uint(sA[r + g][sk + t]);
                a1[mt] = __float_as_uint(sA[r + g + 8][sk + t]);
                a2[mt] = __float_as_uint(sA[r + g][sk + t + 4]);
                a3[mt] = __float_as_uint(sA[r + g + 8][sk + t + 4]);
            }
#pragma unroll
            for (int j = 0; j < 3; j++) {
                int n0 = wn * 24 + j * 8;
                unsigned b0v = __float_as_uint(sW[sk + t][n0 + g]);
                unsigned b1v = __float_as_uint(sW[sk + t + 4][n0 + g]);
                mma8(acc[0][j], a0[0], a1[0], a2[0], a3[0], b0v, b1v);
                mma8(acc[1][j], a0[1], a1[1], a2[1], a3[1], b0v, b1v);
            }
        }
        __syncthreads();
    }
    float* vp = g_pool + OF_VOLP;
#pragma unroll
    for (int mt = 0; mt < 2; mt++) {
        int r0 = row0 + mrow + mt * 16 + g, r1 = r0 + 8;
#pragma unroll
        for (int j = 0; j < 3; j++) {
            int c = wn * 24 + j * 8 + 2 * t;
            float bx = pb[c], by = pb[c + 1];
            *(float2*)&vp[(size_t)r0 * 96 + c] = make_float2(acc[mt][j].x + bx, acc[mt][j].y + by);
            *(float2*)&vp[(size_t)r1 * 96 + c] = make_float2(acc[mt][j].z + bx, acc[mt][j].w + by);
        }
    }
}

// ============================================================
// K7a: qkv GEMM, K-chunk 16 double-buffered
// ============================================================
__global__ __launch_bounds__(256) void k_qkv(const float* __restrict__ qb)
{
    extern __shared__ float sm[];
    float* sAb[2] = { sm, sm + 1280 };
    float* sWb[2] = { sm + 2560, sm + 2560 + 4736 };
    const float* A = g_pool + OF_XATT;
    const float* wq = g_pool + OF_WQKV;
    const int tid = threadIdx.x, warp = tid >> 5, lane = tid & 31;
    const int g = lane >> 2, t = lane & 3;
    const int wm = warp >> 2, wn = warp & 3;
    const int row0 = blockIdx.x * 64;
    const int mrow = wm * 32;
    const int ar = tid >> 2, ac = (tid & 3) * 4;

    float4 acc[2][9];
#pragma unroll
    for (int mt = 0; mt < 2; mt++)
#pragma unroll
        for (int j = 0; j < 9; j++) acc[mt][j] = make_float4(0.f, 0.f, 0.f, 0.f);

    {
        cpa16(sAb[0] + ar * 20 + ac, A + (size_t)(row0 + ar) * 96 + ac);
#pragma unroll
        for (int i = 0; i < 5; i++) {
            int idx = tid + i * 256;
            if (idx < 1152) {
                int r = idx / 72, c = (idx % 72) * 4;
                cpa16(sWb[0] + r * 296 + c, wq + (size_t)r * 288 + c);
            }
        }
        CP_COMMIT();
    }

    for (int it = 0; it < 6; it++) {
        int buf = it & 1;
        if (it < 5) {
            int kb = (it + 1) * 16, nb = buf ^ 1;
            cpa16(sAb[nb] + ar * 20 + ac, A + (size_t)(row0 + ar) * 96 + kb + ac);
#pragma unroll
            for (int i = 0; i < 5; i++) {
                int idx = tid + i * 256;
                if (idx < 1152) {
                    int r = idx / 72, c = (idx % 72) * 4;
                    cpa16(sWb[nb] + r * 296 + c, wq + (size_t)(kb + r) * 288 + c);
                }
            }
            CP_COMMIT();
            CP_WAIT1();
        } else {
            CP_WAIT0();
        }
        __syncthreads();
        const float* sA = sAb[buf];
        const float* sW = sWb[buf];
#pragma unroll
        for (int sk = 0; sk < 16; sk += 8) {
            unsigned a0[2], a1[2], a2[2], a3[2];
#pragma unroll
            for (int mt = 0; mt < 2; mt++) {
                int r = mrow + mt * 16;
                a0[mt] = __float_as_uint(sA[(r + g) * 20 + sk + t]);
                a1[mt] = __float_as_uint(sA[(r + g + 8) * 20 + sk + t]);
                a2[mt] = __float_as_uint(sA[(r + g) * 20 + sk + t + 4]);
                a3[mt] = __float_as_uint(sA[(r + g + 8) * 20 + sk + t + 4]);
            }
#pragma unroll
            for (int j = 0; j < 9; j++) {
                int n0 = wn * 72 + j * 8;
                unsigned b0v = __float_as_uint(sW[(sk + t) * 296 + n0 + g]);
                unsigned b1v = __float_as_uint(sW[(sk + t + 4) * 296 + n0 + g]);
                mma8(acc[0][j], a0[0], a1[0], a2[0], a3[0], b0v, b1v);
                mma8(acc[1][j], a0[1], a1[1], a2[1], a3[1], b0v, b1v);
            }
        }
        __syncthreads();
    }
    float* Q = g_pool + OF_QKV + (size_t)blockIdx.x * 18432;
    const float* gate = g_pool + OF_GATE + (blockIdx.x >> 9) * 96;
#pragma unroll
    for (int mt = 0; mt < 2; mt++) {
        int n0r = mrow + mt * 16 + g, n1r = n0r + 8;
#pragma unroll
        for (int j = 0; j < 9; j++) {
            int c = wn * 72 + j * 8 + 2 * t;
            int s = c / 96, rem = c - s * 96, h = rem >> 4, d = rem & 15;
            float bx = qb[c], by = qb[c + 1];
            float x0 = acc[mt][j].x + bx, y0 = acc[mt][j].y + by;
            float z0 = acc[mt][j].z + bx, w0 = acc[mt][j].w + by;
            if (s == 0) { x0 *= 0.25f; y0 *= 0.25f; z0 *= 0.25f; w0 *= 0.25f; }
            else if (s == 2) {
                float g0 = gate[rem], g1 = gate[rem + 1];
                x0 *= g0; y0 *= g1; z0 *= g0; w0 *= g1;
            }
            float* dst = Q + s * 6144 + h * 1024 + d;
            *(float2*)(dst + n0r * 16) = make_float2(x0, y0);
            *(float2*)(dst + n1r * 16) = make_float2(z0, w0);
        }
    }
}

// ============================================================
// K7b: attention per window (vectorized smem, pad 20)
// ============================================================
__global__ __launch_bounds__(256) void k_attn()
{
    __shared__ float qS[64][20], kS[64][20], vS[64][20];
    __shared__ float pS[64][65];
    int tid = threadIdx.x;
    int win = blockIdx.x;
    const float* qkv = g_pool + OF_QKV + (size_t)win * 18432;
    const float* biasT = g_pool + OF_BIAS;
    float* out = g_pool + OF_AOUT + (size_t)win * 64 * 96;
    int warp = tid >> 5, lane = tid & 31;
    int sn = tid >> 2, sd = (tid & 3) * 4;

    for (int hh = 0; hh < 6; hh++) {
        {
            const float* base = qkv + hh * 1024 + sn * 16 + sd;
            *(float4*)&qS[sn][sd] = *(const float4*)(base);
            *(float4*)&kS[sn][sd] = *(const float4*)(base + 6144);
            *(float4*)&vS[sn][sd] = *(const float4*)(base + 12288);
        }
        __syncthreads();
        for (int rr = 0; rr < 8; rr++) {
            int n = warp * 8 + rr;
            int m0 = lane, m1 = lane + 32;
            float s0 = biasT[hh * 4096 + n * 64 + m0];
            float s1 = biasT[hh * 4096 + n * 64 + m1];
#pragma unroll
            for (int d4 = 0; d4 < 4; d4++) {
                float4 qv = *(const float4*)&qS[n][d4 * 4];
                float4 k0 = *(const float4*)&kS[m0][d4 * 4];
                float4 k1 = *(const float4*)&kS[m1][d4 * 4];
                s0 += qv.x * k0.x + qv.y * k0.y + qv.z * k0.z + qv.w * k0.w;
                s1 += qv.x * k1.x + qv.y * k1.y + qv.z * k1.z + qv.w * k1.w;
            }
            float mx = fmaxf(s0, s1);
#pragma unroll
            for (int o = 16; o; o >>= 1) mx = fmaxf(mx, __shfl_xor_sync(~0u, mx, o));
            float e0 = expf(s0 - mx), e1 = expf(s1 - mx);
            float sum = e0 + e1;
#pragma unroll
            for (int o = 16; o; o >>= 1) sum += __shfl_xor_sync(~0u, sum, o);
            float inv = 1.f / sum;
            pS[n][m0] = e0 * inv;
            pS[n][m1] = e1 * inv;
        }
        __syncthreads();
        {
            int n = tid >> 2, dg = tid & 3;
            float a0 = 0.f, a1 = 0.f, a2 = 0.f, a3 = 0.f;
#pragma unroll
            for (int m = 0; m < 64; m++) {
                float pm = pS[n][m];
                float4 v = *(const float4*)&vS[m][dg * 4];
                a0 += pm * v.x; a1 += pm * v.y; a2 += pm * v.z; a3 += pm * v.w;
            }
            size_t ob = (size_t)n * 96 + hh * 16 + dg * 4;
            *(float4*)(out + ob) = make_float4(a0, a1, a2, a3);
        }
        __syncthreads();
    }
}

// ============================================================
// K8a: si stage 1
// ============================================================
__global__ __launch_bounds__(256) void k_si1(
    const float* __restrict__ w1, const float* __restrict__ b1)
{
    __shared__ float aS[64][97];
    __shared__ float wS[96 * 12];
    __shared__ float sb[64][12];
    int tid = threadIdx.x;
    int blk = blockIdx.x; int row0 = blk * 64;
    const float* A = g_pool + OF_AOUT;
    for (int i = tid; i < 96 * 12; i += 256) wS[i] = w1[i];
    for (int i = tid; i < 64 * 96; i += 256) {
        int r = i / 96, c = i % 96;
        aS[r][c] = A[(size_t)(row0 + r) * 96 + c];
    }
    __syncthreads();
    {
        int r = tid >> 2, jg = tid & 3;
        float s0 = b1[jg * 3 + 0], s1 = b1[jg * 3 + 1], s2 = b1[jg * 3 + 2];
        for (int c = 0; c < 96; c++) {
            float a = aS[r][c];
            s0 += a * wS[c * 12 + jg * 3 + 0];
            s1 += a * wS[c * 12 + jg * 3 + 1];
            s2 += a * wS[c * 12 + jg * 3 + 2];
        }
        float* o = g_pool + OF_S12 + (size_t)(row0 + r) * 12 + jg * 3;
        o[0] = s0; o[1] = s1; o[2] = s2;
        sb[r][jg * 3 + 0] = s0; sb[r][jg * 3 + 1] = s1; sb[r][jg * 3 + 2] = s2;
    }
    __syncthreads();
    if (tid < 12) {
        float S = 0.f, Q = 0.f;
        for (int r = 0; r < 64; r++) { float v = sb[r][tid]; S += v; Q += v * v; }
        g_pool[OF_P12S + (size_t)blk * 12 + tid] = S;
        g_pool[OF_P12Q + (size_t)blk * 12 + tid] = Q;
    }
}

// ============================================================
// K8c: gate + multiply + partials
// ============================================================
__global__ __launch_bounds__(96) void k_gatemul(
    const float* __restrict__ w2, const float* __restrict__ b2)
{
    __shared__ float gb[64];
    int tid = threadIdx.x;
    int blk = blockIdx.x; int row0 = blk * 64; int b = row0 >> 15;
    if (tid < 64) {
        const float* s = g_pool + OF_S12 + (size_t)(row0 + tid) * 12;
        float a = b2[0];
#pragma unroll
        for (int j = 0; j < 12; j++) {
            float v = (s[j] - g_pool[OF_M2 + b * 12 + j]) * g_pool[OF_R2 + b * 12 + j];
            a += geluf(v) * w2[j];
        }
        gb[tid] = 1.f / (1.f + expf(-a));
    }
    __syncthreads();
    const float* vp = g_pool + OF_VOLP + (size_t)row0 * 96 + tid;
    float* yv = g_pool + OF_YV + (size_t)row0 * 96 + tid;
    float ss = 0.f, sq = 0.f;
    for (int r = 0; r < 64; r++) {
        float y = gb[r] * vp[(size_t)r * 96];
        yv[(size_t)r * 96] = y;
        ss += y; sq += y * y;
    }
    g_pool[OF_PYS + (size_t)blk * 96 + tid] = ss;
    g_pool[OF_PYQ + (size_t)blk * 96 + tid] = sq;
}

// ============================================================
// K9: final (tf32 mma, K-chunk 16 double-buffered W, 3 CTA/SM)
// ============================================================
__global__ __launch_bounds__(256, 3) void k_final(
    const float* __restrict__ bp,
    const float* __restrict__ ga, const float* __restrict__ ba,
    float* __restrict__ out)
{
    extern __shared__ float sm[];
    float (*sA)[196] = (float(*)[196])sm;
    float* sWb[2] = { sm + 12544, sm + 12544 + 3200 };
    const float* wp = g_pool + OF_WPROJ;
    const int tid = threadIdx.x, warp = tid >> 5, lane = tid & 31;
    const int g = lane >> 2, t = lane & 3;
    const int wm = warp >> 2, wn = warp & 3;
    const int row0 = blockIdx.x * 64; const int b = row0 >> 15;
    const int mrow = wm * 32;
    const float* A = g_pool + OF_AOUT;
    const float* Y = g_pool + OF_YV;

    {
#pragma unroll
        for (int i = 0; i < 3; i++) {
            int idx = tid + i * 256; int r = idx / 48, c = (idx % 48) * 4;
            cpa16(sWb[0] + r * 200 + c, wp + (size_t)r * 192 + c);
        }
        CP_COMMIT();
    }

    for (int it = 0; it < 8; it++) {
        int r = warp * 8 + it;
        int row = row0 + r;
        float s = 0.f, q = 0.f;
        float vals[3];
#pragma unroll
        for (int i = 0; i < 3; i++) {
            vals[i] = A[(size_t)row * 96 + lane + 32 * i];
            s += vals[i]; q += vals[i] * vals[i];
        }
#pragma unroll
        for (int o = 16; o; o >>= 1) { s += __shfl_xor_sync(~0u, s, o); q += __shfl_xor_sync(~0u, q, o); }
        float m = s * (1.f / 96.f);
        float rs = rsqrtf(fmaxf(q * (1.f / 96.f) - m * m, 0.f) + EPS);
#pragma unroll
        for (int i = 0; i < 3; i++) {
            int c = lane + 32 * i;
            sA[r][c] = tf32f((vals[i] - m) * rs * ga[c] + ba[c]);
        }
#pragma unroll
        for (int i = 0; i < 3; i++) {
            int c = lane + 32 * i;
            float v = (Y[(size_t)row * 96 + c] - g_pool[OF_M3 + b * 96 + c]) * g_pool[OF_R3 + b * 96 + c];
            sA[r][96 + c] = tf32f(v);
        }
    }
    __syncthreads();

    float4 acc[2][6];
#pragma unroll
    for (int mt = 0; mt < 2; mt++)
#pragma unroll
        for (int j = 0; j < 6; j++) acc[mt][j] = make_float4(0.f, 0.f, 0.f, 0.f);

    for (int it = 0; it < 12; it++) {
        int buf = it & 1;
        int kb = it * 16;
        if (it < 11) {
            int nkb = kb + 16, nb = buf ^ 1;
#pragma unroll
            for (int i = 0; i < 3; i++) {
                int idx = tid + i * 256; int r = idx / 48, c = (idx % 48) * 4;
                cpa16(sWb[nb] + r * 200 + c, wp + (size_t)(nkb + r) * 192 + c);
            }
            CP_COMMIT();
            CP_WAIT1();
        } else {
            CP_WAIT0();
        }
        __syncthreads();
        const float* sW = sWb[buf];
#pragma unroll
        for (int sk = 0; sk < 16; sk += 8) {
            unsigned a0[2], a1[2], a2[2], a3[2];
#pragma unroll
            for (int mt = 0; mt < 2; mt++) {
                int r = mrow + mt * 16;
                a0[mt] = __float_as_uint(sA[r + g][kb + sk + t]);
                a1[mt] = __float_as_uint(sA[r + g + 8][kb + sk + t]);
                a2[mt] = __float_as_uint(sA[r + g][kb + sk + t + 4]);
                a3[mt] = __float_as_uint(sA[r + g + 8][kb + sk + t + 4]);
            }
#pragma unroll
            for (int j = 0; j < 6; j++) {
                int n0 = wn * 48 + j * 8;
                unsigned b0v = __float_as_uint(sW[(sk + t) * 200 + n0 + g]);
                unsigned b1v = __float_as_uint(sW[(sk + t + 4) * 200 + n0 + g]);
                mma8(acc[0][j], a0[0], a1[0], a2[0], a3[0], b0v, b1v);
                mma8(acc[1][j], a0[1], a1[1], a2[1], a3[1], b0v, b1v);
            }
        }
        __syncthreads();
    }
#pragma unroll
    for (int mt = 0; mt < 2; mt++) {
        int r0 = row0 + mrow + mt * 16 + g, r1 = r0 + 8;
#pragma unroll
        for (int j = 0; j < 6; j++) {
            int c = wn * 48 + j * 8 + 2 * t;
            float bx = bp[c], by = bp[c + 1];
            *(float2*)&out[(size_t)r0 * 192 + c] = make_float2(acc[mt][j].x + bx, acc[mt][j].y + by);
            *(float2*)&out[(size_t)r1 * 192 + c] = make_float2(acc[mt][j].z + bx, acc[mt][j].w + by);
        }
    }
}

// ============================================================
// host launcher
// ============================================================
extern "C" void kernel_launch(void* const* d_in, const int* in_sizes, int n_in,
                              void* d_out, int out_size)
{
    const float* x       = (const float*)d_in[0];
    const float* w_pattn = (const float*)d_in[1];
    const float* b_pattn = (const float*)d_in[2];
    const float* g_aln   = (const float*)d_in[3];
    const float* b_aln   = (const float*)d_in[4];
    const float* w_pcnn  = (const float*)d_in[5];
    const float* b_pcnn  = (const float*)d_in[6];
    const float* g_cln   = (const float*)d_in[7];
    const float* b_cln   = (const float*)d_in[8];
    const float* dw_w    = (const float*)d_in[9];
    const float* dw_b    = (const float*)d_in[10];
    const float* ci_w1   = (const float*)d_in[11];
    const float* ci_b1   = (const float*)d_in[12];
    const float* ci_w2   = (const float*)d_in[13];
    const float* ci_b2   = (const float*)d_in[14];
    const float* pj_w    = (const float*)d_in[15];
    const float* pj_b    = (const float*)d_in[16];
    const float* qkv_w   = (const float*)d_in[17];
    const float* qkv_b   = (const float*)d_in[18];
    const float* si_w1   = (const float*)d_in[19];
    const float* si_b1   = (const float*)d_in[20];
    const float* si_w2   = (const float*)d_in[21];
    const float* si_b2   = (const float*)d_in[22];
    const float* g_anorm = (const float*)d_in[23];
    const float* b_anorm = (const float*)d_in[24];
    const float* w_proj  = (const float*)d_in[25];
    const float* b_proj  = (const float*)d_in[26];
    const float* rpb     = (const float*)d_in[27];

    const int Bwin = in_sizes[0] / (64 * 192);   // 2048
    const int rows = Bwin * 64;                  // 131072
    const int nb   = Bwin / 512;                 // 4

    cudaFuncSetAttribute(k_embed, cudaFuncAttributeMaxDynamicSharedMemorySize, 75776);
    cudaFuncSetAttribute(k_qkv,   cudaFuncAttributeMaxDynamicSharedMemorySize, 50176);
    cudaFuncSetAttribute(k_final, cudaFuncAttributeMaxDynamicSharedMemorySize, 77824);

    // k_dwconv at launch index 3 (ncu capture slot)
    k_wprep<<<216, 256>>>(w_pattn, w_pcnn, qkv_w, w_proj, pj_w);
    k_bias<<<6, 256>>>(rpb);
    k_embed<<<rows / 64, 256, 73728>>>(x, b_pattn, g_aln, b_aln,
                                       b_pcnn, g_cln, b_cln);
    k_dwconv<<<nb * 512, 192>>>(dw_w, dw_b);
    k_redstats<<<nb * 192, 128>>>(OF_PCS, OF_PCQ, 1024, 192, 1.f / 32768.f, OF_M1, OF_R1);
    k_pool<<<nb * 1024, 192>>>();
    k_redmean<<<nb * 192, 128>>>(OF_PPOOL, 1024, 192, 1.f / 32768.f, OF_POOLED);
    k_ci<<<1, 96>>>(ci_w1, ci_b1, ci_w2, ci_b2, nb);
    k_pj<<<rows / 64, 256>>>(pj_b);
    k_qkv<<<rows / 64, 256, 48128>>>(qkv_b);
    k_attn<<<Bwin, 256>>>();
    k_si1<<<rows / 64, 256>>>(si_w1, si_b1);
    k_redstats<<<nb * 12, 128>>>(OF_P12S, OF_P12Q, 512, 12, 1.f / 32768.f, OF_M2, OF_R2);
    k_gatemul<<<rows / 64, 96>>>(si_w2, si_b2);
    k_redstats<<<nb * 96, 128>>>(OF_PYS, OF_PYQ, 512, 96, 1.f / 32768.f, OF_M3, OF_R3);
    k_final<<<rows / 64, 256, 75776>>>(b_proj, g_anorm, b_anorm, (float*)d_out);
}